// round 11
// baseline (speedup 1.0000x reference)
#include <cuda_runtime.h>
#include <cuda_bf16.h>
#include <cstdint>
#include <cstddef>

// Problem constants (fixed by the dataset)
#define BB 4
#define TT 2048
#define CC 1024
#define HH 16
#define DD 64
#define RR 8
#define MM (BB*TT)        // 8192
#define NQKV (3*CC)       // 3072

// Scratch (device globals -- referenced ONLY from device code).
__device__ float g_y[(size_t)MM*CC];         // attention output [B,T,C]
__device__ float g_t[(size_t)MM*RR];         // LoRA intermediate x@A^T
__device__ __nv_bfloat16 g_ah[(size_t)MM*CC];     // x, then attention y (hi)
__device__ __nv_bfloat16 g_al[(size_t)MM*CC];     // (lo)
__device__ __nv_bfloat16 g_bh[(size_t)NQKV*CC];   // c_attn_w hi
__device__ __nv_bfloat16 g_bl[(size_t)NQKV*CC];   // c_attn_w lo
__device__ __nv_bfloat16 g_pwh[(size_t)CC*CC];    // c_proj_w hi
__device__ __nv_bfloat16 g_pwl[(size_t)CC*CC];    // c_proj_w lo
// q/k/v in [B,H,T,D] as bf16 hi/lo split
__device__ __nv_bfloat16 g_qh[(size_t)BB*HH*TT*DD];
__device__ __nv_bfloat16 g_ql[(size_t)BB*HH*TT*DD];
__device__ __nv_bfloat16 g_kh[(size_t)BB*HH*TT*DD];
__device__ __nv_bfloat16 g_kl[(size_t)BB*HH*TT*DD];
__device__ __nv_bfloat16 g_vh[(size_t)BB*HH*TT*DD];
__device__ __nv_bfloat16 g_vl[(size_t)BB*HH*TT*DD];

// ---------------------------------------------------------------------------
// Helpers (base-target ISA only: cp.async / ldmatrix / mma.sync)
// ---------------------------------------------------------------------------
__device__ __forceinline__ uint32_t smem_u32(const void* p) {
    uint32_t a;
    asm("{ .reg .u64 t; cvta.to.shared.u64 t, %1; cvt.u32.u64 %0, t; }"
        : "=r"(a) : "l"(p));
    return a;
}
#define SWZ128(off) ((off) ^ (((off) >> 3) & 0x70))

#define CP_ASYNC16(dst, src) \
    asm volatile("cp.async.cg.shared.global [%0], [%1], 16;" :: "r"(dst), "l"(src))
#define CP_COMMIT() asm volatile("cp.async.commit_group;" ::: "memory")
#define CP_WAIT(n)  asm volatile("cp.async.wait_group %0;" :: "n"(n) : "memory")

#define LDSM_X4(r, a) \
    asm volatile("ldmatrix.sync.aligned.m8n8.x4.shared.b16 {%0,%1,%2,%3}, [%4];" \
                 : "=r"((r)[0]), "=r"((r)[1]), "=r"((r)[2]), "=r"((r)[3]) : "r"(a))
#define LDSM_X4_T(r, a) \
    asm volatile("ldmatrix.sync.aligned.m8n8.x4.trans.shared.b16 {%0,%1,%2,%3}, [%4];" \
                 : "=r"((r)[0]), "=r"((r)[1]), "=r"((r)[2]), "=r"((r)[3]) : "r"(a))

#define MMA16816(d, a, b0, b1) \
    asm volatile("mma.sync.aligned.m16n8k16.row.col.f32.bf16.bf16.f32 " \
                 "{%0,%1,%2,%3}, {%4,%5,%6,%7}, {%8,%9}, {%0,%1,%2,%3};" \
                 : "+f"((d)[0]), "+f"((d)[1]), "+f"((d)[2]), "+f"((d)[3]) \
                 : "r"((a)[0]), "r"((a)[1]), "r"((a)[2]), "r"((a)[3]), \
                   "r"(b0), "r"(b1))

// split a float pair into bf16 hi pair + bf16 lo (residual) pair
__device__ __forceinline__ void split_pair(float a, float b, uint32_t& hi, uint32_t& lo) {
    __nv_bfloat162 h = __floats2bfloat162_rn(a, b);
    float ra = a - __bfloat162float(h.x);
    float rb = b - __bfloat162float(h.y);
    __nv_bfloat162 l = __floats2bfloat162_rn(ra, rb);
    hi = *(uint32_t*)&h;
    lo = *(uint32_t*)&l;
}

// ---------------------------------------------------------------------------
// fp32 -> bf16 hi/lo split conversion. DST selects device-global target
// INSIDE device code: 0 -> g_ah/g_al, 1 -> g_bh/g_bl, 2 -> g_pwh/g_pwl.
// ---------------------------------------------------------------------------
template<int DST>
__global__ void conv_split(const float* __restrict__ src, int n4) {
    int i = blockIdx.x * blockDim.x + threadIdx.x;
    if (i >= n4) return;
    float4 v = ((const float4*)src)[i];
    __nv_bfloat16* H = (DST == 0) ? g_ah : ((DST == 1) ? g_bh : g_pwh);
    __nv_bfloat16* L = (DST == 0) ? g_al : ((DST == 1) ? g_bl : g_pwl);
    uint32_t h0, l0, h1, l1;
    split_pair(v.x, v.y, h0, l0);
    split_pair(v.z, v.w, h1, l1);
    ((uint32_t*)H)[2*i]   = h0;
    ((uint32_t*)H)[2*i+1] = h1;
    ((uint32_t*)L)[2*i]   = l0;
    ((uint32_t*)L)[2*i+1] = l1;
}

// ---------------------------------------------------------------------------
// LoRA intermediate: t[m, r] = sum_k X[m,k] * A[r,k]   (one warp per row m)
// ---------------------------------------------------------------------------
template<int SRC>
__global__ void lora_kernel(const float* __restrict__ Xin, const float* __restrict__ A) {
    const float* X = (SRC == 1) ? g_y : Xin;
    int warp = (blockIdx.x * blockDim.x + threadIdx.x) >> 5;
    int lane = threadIdx.x & 31;
    const float* xr = X + (size_t)warp * CC;
    float acc[RR];
#pragma unroll
    for (int r = 0; r < RR; r++) acc[r] = 0.f;
    for (int k = lane; k < CC; k += 32) {
        float xv = xr[k];
#pragma unroll
        for (int r = 0; r < RR; r++) acc[r] = fmaf(xv, __ldg(&A[r*CC + k]), acc[r]);
    }
#pragma unroll
    for (int r = 0; r < RR; r++) {
        acc[r] += __shfl_xor_sync(0xffffffffu, acc[r], 16);
        acc[r] += __shfl_xor_sync(0xffffffffu, acc[r], 8);
        acc[r] += __shfl_xor_sync(0xffffffffu, acc[r], 4);
        acc[r] += __shfl_xor_sync(0xffffffffu, acc[r], 2);
        acc[r] += __shfl_xor_sync(0xffffffffu, acc[r], 1);
    }
    if (lane == 0) {
#pragma unroll
        for (int r = 0; r < RR; r++) g_t[(size_t)warp*RR + r] = acc[r];
    }
}

// ---------------------------------------------------------------------------
// bf16-split HMMA GEMM (mma.sync m16n8k16) + bias + rank-8 LoRA epilogue.
// CTA tile 128(M) x 256(N), 256 threads: 8 warps of 64x64, term-major MMAs.
// K chunks of 64, double-buffered cp.async, stage = 96KB, smem 193KB.
// MODE 0: QKV (weights g_bh/g_bl) -> q/k/v hi/lo scatter + query/key outs.
// MODE 1: proj (weights g_pwh/g_pwl) -> plain [M,C] fp32 output.
// ---------------------------------------------------------------------------
#define STAGE_BYTES 98304
#define OFF_AH 0
#define OFF_AL 16384
#define OFF_BH 32768
#define OFF_BL 65536

template<int MODE>
__global__ void __launch_bounds__(256) mma_gemm(const float* __restrict__ bias,
                                                const float* __restrict__ Blora,
                                                float* __restrict__ out0,
                                                float* __restrict__ out1)
{
    extern __shared__ char smem_raw[];
    uint32_t raw = smem_u32(smem_raw);
    uint32_t sb = (raw + 1023u) & ~1023u;

    const __nv_bfloat16* Wh = (MODE == 0) ? g_bh : g_pwh;   // device-side select
    const __nv_bfloat16* Wl = (MODE == 0) ? g_bl : g_pwl;

    int tid  = threadIdx.x;
    int wid  = tid >> 5, lane = tid & 31;
    int wm   = wid >> 2;       // 0..1 -> 64-row slab
    int wn   = wid & 3;        // 0..3 -> 64-col slab
    int bm = blockIdx.y * 128;
    int bn = blockIdx.x * 256;

    int lrow = tid >> 3;       // 0..31
    int lq   = tid & 7;        // uint4 index within 128B row

    float acc[4][8][4];
#pragma unroll
    for (int i = 0; i < 4; i++)
#pragma unroll
        for (int j = 0; j < 8; j++)
#pragma unroll
            for (int c = 0; c < 4; c++) acc[i][j][c] = 0.f;

    auto load_chunk = [&](int stage, int k0) {
        uint32_t base = sb + stage * STAGE_BYTES;
#pragma unroll
        for (int i = 0; i < 4; i++) {
            int row = lrow + i * 32;
            uint32_t boff = SWZ128((uint32_t)(row * 128 + lq * 16));
            size_t go = (size_t)(bm + row) * CC + k0 + lq * 8;
            CP_ASYNC16(base + OFF_AH + boff, g_ah + go);
            CP_ASYNC16(base + OFF_AL + boff, g_al + go);
        }
#pragma unroll
        for (int i = 0; i < 8; i++) {
            int row = lrow + i * 32;
            uint32_t boff = SWZ128((uint32_t)(row * 128 + lq * 16));
            size_t go = (size_t)(bn + row) * CC + k0 + lq * 8;
            CP_ASYNC16(base + OFF_BH + boff, Wh + go);
            CP_ASYNC16(base + OFF_BL + boff, Wl + go);
        }
        CP_COMMIT();
    };

    const int NCHUNK = CC / 64;
    load_chunk(0, 0);

    for (int ch = 0; ch < NCHUNK; ++ch) {
        if (ch + 1 < NCHUNK) {
            load_chunk((ch + 1) & 1, (ch + 1) * 64);
            CP_WAIT(1);
        } else {
            CP_WAIT(0);
        }
        __syncthreads();
        uint32_t base = sb + (ch & 1) * STAGE_BYTES;

#pragma unroll
        for (int ks = 0; ks < 4; ks++) {
            uint32_t ah[4][4], al[4][4];
#pragma unroll
            for (int ma = 0; ma < 4; ma++) {
                int row = wm * 64 + ma * 16 + (lane & 15);
                uint32_t kb = ks * 32 + ((lane >> 4) << 4);
                uint32_t off = SWZ128((uint32_t)(row * 128) + kb);
                LDSM_X4(ah[ma], base + OFF_AH + off);
                LDSM_X4(al[ma], base + OFF_AL + off);
            }
#pragma unroll
            for (int nb = 0; nb < 4; nb++) {
                uint32_t bh4[4], bl4[4];
                int row = wn * 64 + nb * 16 + (lane & 7) + ((lane >> 4) << 3);
                uint32_t kb = ks * 32 + (((lane >> 3) & 1) << 4);
                uint32_t off = SWZ128((uint32_t)(row * 128) + kb);
                LDSM_X4(bh4, base + OFF_BH + off);
                LDSM_X4(bl4, base + OFF_BL + off);
#pragma unroll
                for (int ma = 0; ma < 4; ma++)
#pragma unroll
                    for (int h = 0; h < 2; h++)
                        MMA16816(acc[ma][nb*2+h], ah[ma], bh4[2*h], bh4[2*h+1]);
#pragma unroll
                for (int ma = 0; ma < 4; ma++)
#pragma unroll
                    for (int h = 0; h < 2; h++)
                        MMA16816(acc[ma][nb*2+h], ah[ma], bl4[2*h], bl4[2*h+1]);
#pragma unroll
                for (int ma = 0; ma < 4; ma++)
#pragma unroll
                    for (int h = 0; h < 2; h++)
                        MMA16816(acc[ma][nb*2+h], al[ma], bh4[2*h], bh4[2*h+1]);
            }
        }
        __syncthreads();
    }

    // ---- epilogue: + bias + LoRA, write out ----
#pragma unroll
    for (int ma = 0; ma < 4; ma++) {
        int m0 = bm + wm * 64 + ma * 16 + (lane >> 2);
        int m1 = m0 + 8;
        float4 t0a = *(const float4*)&g_t[(size_t)m0 * RR];
        float4 t0b = *(const float4*)&g_t[(size_t)m0 * RR + 4];
        float4 t1a = *(const float4*)&g_t[(size_t)m1 * RR];
        float4 t1b = *(const float4*)&g_t[(size_t)m1 * RR + 4];
#pragma unroll
        for (int na = 0; na < 8; na++) {
            int n0 = bn + wn * 64 + na * 8 + (lane & 3) * 2;
            int n1 = n0 + 1;
            float4 b0a = *(const float4*)&Blora[(size_t)n0 * RR];
            float4 b0b = *(const float4*)&Blora[(size_t)n0 * RR + 4];
            float4 b1a = *(const float4*)&Blora[(size_t)n1 * RR];
            float4 b1b = *(const float4*)&Blora[(size_t)n1 * RR + 4];
            float bs0 = __ldg(&bias[n0]), bs1 = __ldg(&bias[n1]);
            float v00 = acc[ma][na][0] + bs0
                + t0a.x*b0a.x + t0a.y*b0a.y + t0a.z*b0a.z + t0a.w*b0a.w
                + t0b.x*b0b.x + t0b.y*b0b.y + t0b.z*b0b.z + t0b.w*b0b.w;
            float v01 = acc[ma][na][1] + bs1
                + t0a.x*b1a.x + t0a.y*b1a.y + t0a.z*b1a.z + t0a.w*b1a.w
                + t0b.x*b1b.x + t0b.y*b1b.y + t0b.z*b1b.z + t0b.w*b1b.w;
            float v10 = acc[ma][na][2] + bs0
                + t1a.x*b0a.x + t1a.y*b0a.y + t1a.z*b0a.z + t1a.w*b0a.w
                + t1b.x*b0b.x + t1b.y*b0b.y + t1b.z*b0b.z + t1b.w*b0b.w;
            float v11 = acc[ma][na][3] + bs1
                + t1a.x*b1a.x + t1a.y*b1a.y + t1a.z*b1a.z + t1a.w*b1a.w
                + t1b.x*b1b.x + t1b.y*b1b.y + t1b.z*b1b.z + t1b.w*b1b.w;

            if (MODE == 0) {
                int sec = n0 >> 10;            // 0=q, 1=k, 2=v
                int cci = n0 & 1023;
                int h = cci >> 6, dd = cci & 63;
                __nv_bfloat16* dh = (sec == 0) ? g_qh : ((sec == 1) ? g_kh : g_vh);
                __nv_bfloat16* dl = (sec == 0) ? g_ql : ((sec == 1) ? g_kl : g_vl);
                {
                    int bi = m0 >> 11, ti = m0 & 2047;
                    size_t idx = ((size_t)((bi*HH) + h)*TT + ti)*DD + dd;
                    uint32_t hp, lp; split_pair(v00, v01, hp, lp);
                    *(uint32_t*)&dh[idx] = hp;
                    *(uint32_t*)&dl[idx] = lp;
                    float2 p; p.x = v00; p.y = v01;
                    if (sec == 0)      *(float2*)&out0[(size_t)m0*CC + cci] = p;
                    else if (sec == 1) *(float2*)&out1[(size_t)m0*CC + cci] = p;
                }
                {
                    int bi = m1 >> 11, ti = m1 & 2047;
                    size_t idx = ((size_t)((bi*HH) + h)*TT + ti)*DD + dd;
                    uint32_t hp, lp; split_pair(v10, v11, hp, lp);
                    *(uint32_t*)&dh[idx] = hp;
                    *(uint32_t*)&dl[idx] = lp;
                    float2 p; p.x = v10; p.y = v11;
                    if (sec == 0)      *(float2*)&out0[(size_t)m1*CC + cci] = p;
                    else if (sec == 1) *(float2*)&out1[(size_t)m1*CC + cci] = p;
                }
            } else {
                float2 p0; p0.x = v00; p0.y = v01;
                float2 p1; p1.x = v10; p1.y = v11;
                *(float2*)&out0[(size_t)m0*CC + n0] = p0;
                *(float2*)&out0[(size_t)m1*CC + n0] = p1;
            }
        }
    }
}

// ---------------------------------------------------------------------------
// Tensor-core causal flash attention v2 (bf16 split, fp32 softmax).
// CTA: 128 Q-rows, 128 threads (4 warps x 32 rows, ma in {0,1}).
// Q kept in smem (hi/lo planes, re-ldsm'd per tile) -> 107 B smem/MMA;
// K/V tiles 64x64 hi/lo, cp.async double-buffered; 2 CTAs/SM (97KB smem).
// ---------------------------------------------------------------------------
#define FQ_H 0
#define FQ_L 16384
#define FKV_BASE 32768
#define FKV_STAGE 32768
#define FKV_KH 0
#define FKV_KL 8192
#define FKV_VH 16384
#define FKV_VL 24576

__global__ void __launch_bounds__(128) flash_mma(float* __restrict__ dummy) {
    extern __shared__ char smem_raw[];
    uint32_t raw = smem_u32(smem_raw);
    uint32_t sb = (raw + 1023u) & ~1023u;

    int bh = blockIdx.y;
    int qi = gridDim.x - 1 - (int)blockIdx.x;   // long blocks first
    int tid = threadIdx.x;
    int wid = tid >> 5, lane = tid & 31;
    int row0 = qi * 128;

    const __nv_bfloat16* Qh = g_qh + ((size_t)bh*TT + row0) * DD;
    const __nv_bfloat16* Ql = g_ql + ((size_t)bh*TT + row0) * DD;
    const __nv_bfloat16* Kh = g_kh + (size_t)bh*TT*DD;
    const __nv_bfloat16* Kl = g_kl + (size_t)bh*TT*DD;
    const __nv_bfloat16* Vh = g_vh + (size_t)bh*TT*DD;
    const __nv_bfloat16* Vl = g_vl + (size_t)bh*TT*DD;

    auto load_tile64 = [&](uint32_t dst, const __nv_bfloat16* src) {
#pragma unroll
        for (int i = 0; i < 4; i++) {
            int e = tid + i * 128;
            int row = e >> 3, q = e & 7;
            CP_ASYNC16(dst + SWZ128((uint32_t)(row * 128 + q * 16)), src + row * 64 + q * 8);
        }
    };
    auto load_tile128 = [&](uint32_t dst, const __nv_bfloat16* src) {
#pragma unroll
        for (int i = 0; i < 8; i++) {
            int e = tid + i * 128;
            int row = e >> 3, q = e & 7;
            CP_ASYNC16(dst + SWZ128((uint32_t)(row * 128 + q * 16)), src + row * 64 + q * 8);
        }
    };
    auto load_kv = [&](int stage, int j) {
        uint32_t base = sb + FKV_BASE + stage * FKV_STAGE;
        size_t o = (size_t)j * 64 * DD;
        load_tile64(base + FKV_KH, Kh + o);
        load_tile64(base + FKV_KL, Kl + o);
        load_tile64(base + FKV_VH, Vh + o);
        load_tile64(base + FKV_VL, Vl + o);
        CP_COMMIT();
    };

    // Q (128 rows, hi+lo) as group 0; KV tile 0 as group 1.
    load_tile128(sb + FQ_H, Qh);
    load_tile128(sb + FQ_L, Ql);
    CP_COMMIT();
    load_kv(0, 0);

    float oacc[2][8][4];
#pragma unroll
    for (int ma = 0; ma < 2; ma++)
#pragma unroll
        for (int i = 0; i < 8; i++)
#pragma unroll
            for (int c = 0; c < 4; c++) oacc[ma][i][c] = 0.f;
    float m_pr[2][2] = { { -1e30f, -1e30f }, { -1e30f, -1e30f } };
    float l_pr[2][2] = { { 0.f, 0.f }, { 0.f, 0.f } };

    int jmax = 2 * qi + 1;
    for (int j = 0; j <= jmax; ++j) {
        if (j < jmax) { load_kv((j + 1) & 1, j + 1); CP_WAIT(1); }
        else          { CP_WAIT(0); }
        __syncthreads();
        uint32_t kvb = sb + FKV_BASE + (j & 1) * FKV_STAGE;

        // ---- S = Q K^T (3-term split), Q re-ldsm'd from smem ----
        float sacc[2][8][4];
#pragma unroll
        for (int ma = 0; ma < 2; ma++)
#pragma unroll
            for (int i = 0; i < 8; i++)
#pragma unroll
                for (int c = 0; c < 4; c++) sacc[ma][i][c] = 0.f;
#pragma unroll
        for (int k = 0; k < 4; k++) {
            uint32_t qhf[2][4], qlf[2][4];
#pragma unroll
            for (int ma = 0; ma < 2; ma++) {
                int row = wid * 32 + ma * 16 + (lane & 15);
                uint32_t kb = k * 32 + ((lane >> 4) << 4);
                uint32_t off = SWZ128((uint32_t)(row * 128) + kb);
                LDSM_X4(qhf[ma], sb + FQ_H + off);
                LDSM_X4(qlf[ma], sb + FQ_L + off);
            }
#pragma unroll
            for (int np = 0; np < 4; np++) {
                uint32_t kh4[4], kl4[4];
                int row = np * 16 + (lane & 7) + ((lane >> 3) & 1) * 8;
                uint32_t col = k * 32 + ((lane >> 4) << 4);
                uint32_t off = SWZ128((uint32_t)(row * 128) + col);
                LDSM_X4(kh4, kvb + FKV_KH + off);
                LDSM_X4(kl4, kvb + FKV_KL + off);
#pragma unroll
                for (int ma = 0; ma < 2; ma++) {
                    MMA16816(sacc[ma][2*np],   qhf[ma], kh4[0], kh4[2]);
                    MMA16816(sacc[ma][2*np+1], qhf[ma], kh4[1], kh4[3]);
                    MMA16816(sacc[ma][2*np],   qhf[ma], kl4[0], kl4[2]);
                    MMA16816(sacc[ma][2*np+1], qhf[ma], kl4[1], kl4[3]);
                    MMA16816(sacc[ma][2*np],   qlf[ma], kh4[0], kh4[2]);
                    MMA16816(sacc[ma][2*np+1], qlf[ma], kh4[1], kh4[3]);
                }
            }
        }

        // ---- scale + causal mask + online softmax (per ma) ----
        bool diag = (j >= 2 * qi);
#pragma unroll
        for (int ma = 0; ma < 2; ma++) {
            int rg0 = row0 + wid * 32 + ma * 16 + (lane >> 2);   // global row (c<2)
            float mx[2] = { -1e30f, -1e30f };
#pragma unroll
            for (int na = 0; na < 8; na++) {
#pragma unroll
                for (int c = 0; c < 4; c++) {
                    float s = sacc[ma][na][c] * 0.125f;
                    if (diag) {
                        int colg = j * 64 + na * 8 + (lane & 3) * 2 + (c & 1);
                        int rowg = rg0 + ((c >> 1) << 3);
                        if (colg > rowg) s = -1e30f;
                    }
                    sacc[ma][na][c] = s;
                    mx[c >> 1] = fmaxf(mx[c >> 1], s);
                }
            }
#pragma unroll
            for (int h = 0; h < 2; h++) {
                mx[h] = fmaxf(mx[h], __shfl_xor_sync(0xffffffffu, mx[h], 1));
                mx[h] = fmaxf(mx[h], __shfl_xor_sync(0xffffffffu, mx[h], 2));
            }
            float m_new[2], alpha[2], lsum[2] = { 0.f, 0.f };
#pragma unroll
            for (int h = 0; h < 2; h++) {
                m_new[h] = fmaxf(m_pr[ma][h], mx[h]);
                alpha[h] = __expf(m_pr[ma][h] - m_new[h]);
                m_pr[ma][h] = m_new[h];
            }
#pragma unroll
            for (int na = 0; na < 8; na++) {
#pragma unroll
                for (int c = 0; c < 4; c++) {
                    float p = __expf(sacc[ma][na][c] - m_new[c >> 1]);
                    sacc[ma][na][c] = p;
                    lsum[c >> 1] += p;
                }
            }
#pragma unroll
            for (int h = 0; h < 2; h++) {
                lsum[h] += __shfl_xor_sync(0xffffffffu, lsum[h], 1);
                lsum[h] += __shfl_xor_sync(0xffffffffu, lsum[h], 2);
                l_pr[ma][h] = l_pr[ma][h] * alpha[h] + lsum[h];
            }
#pragma unroll
            for (int na = 0; na < 8; na++) {
                oacc[ma][na][0] *= alpha[0]; oacc[ma][na][1] *= alpha[0];
                oacc[ma][na][2] *= alpha[1]; oacc[ma][na][3] *= alpha[1];
            }
        }

        // ---- O += P V (3-term split) ----
#pragma unroll
        for (int s = 0; s < 4; s++) {
            uint32_t ph[2][4], pl[2][4];
#pragma unroll
            for (int ma = 0; ma < 2; ma++) {
                split_pair(sacc[ma][2*s][0],   sacc[ma][2*s][1],   ph[ma][0], pl[ma][0]);
                split_pair(sacc[ma][2*s][2],   sacc[ma][2*s][3],   ph[ma][1], pl[ma][1]);
                split_pair(sacc[ma][2*s+1][0], sacc[ma][2*s+1][1], ph[ma][2], pl[ma][2]);
                split_pair(sacc[ma][2*s+1][2], sacc[ma][2*s+1][3], ph[ma][3], pl[ma][3]);
            }
#pragma unroll
            for (int np = 0; np < 4; np++) {
                uint32_t vh4[4], vl4[4];
                int row = s * 16 + (lane & 7) + ((lane >> 3) & 1) * 8;
                uint32_t col = np * 32 + ((lane >> 4) << 4);
                uint32_t off = SWZ128((uint32_t)(row * 128) + col);
                LDSM_X4_T(vh4, kvb + FKV_VH + off);
                LDSM_X4_T(vl4, kvb + FKV_VL + off);
#pragma unroll
                for (int ma = 0; ma < 2; ma++) {
                    MMA16816(oacc[ma][2*np],   ph[ma], vh4[0], vh4[1]);
                    MMA16816(oacc[ma][2*np+1], ph[ma], vh4[2], vh4[3]);
                    MMA16816(oacc[ma][2*np],   ph[ma], vl4[0], vl4[1]);
                    MMA16816(oacc[ma][2*np+1], ph[ma], vl4[2], vl4[3]);
                    MMA16816(oacc[ma][2*np],   pl[ma], vh4[0], vh4[1]);
                    MMA16816(oacc[ma][2*np+1], pl[ma], vh4[2], vh4[3]);
                }
            }
        }
        __syncthreads();
    }

    // ---- epilogue: normalize, write fp32 g_y + bf16 split g_ah/g_al ----
    int h = bh & (HH - 1), bi = bh >> 4;
#pragma unroll
    for (int ma = 0; ma < 2; ma++) {
        float inv0 = 1.0f / l_pr[ma][0];
        float inv1 = 1.0f / l_pr[ma][1];
        int t0 = row0 + wid * 32 + ma * 16 + (lane >> 2);
        int t1 = t0 + 8;
        int dbase = h * DD + (lane & 3) * 2;
#pragma unroll
        for (int na = 0; na < 8; na++) {
            int d = dbase + na * 8;
            size_t i0 = ((size_t)(bi*TT + t0))*CC + d;
            size_t i1 = ((size_t)(bi*TT + t1))*CC + d;
            float v00 = oacc[ma][na][0]*inv0, v01 = oacc[ma][na][1]*inv0;
            float v10 = oacc[ma][na][2]*inv1, v11 = oacc[ma][na][3]*inv1;
            float2 p0; p0.x = v00; p0.y = v01;
            float2 p1; p1.x = v10; p1.y = v11;
            *(float2*)&g_y[i0] = p0;
            *(float2*)&g_y[i1] = p1;
            uint32_t hp, lp;
            split_pair(v00, v01, hp, lp);
            *(uint32_t*)&g_ah[i0] = hp; *(uint32_t*)&g_al[i0] = lp;
            split_pair(v10, v11, hp, lp);
            *(uint32_t*)&g_ah[i1] = hp; *(uint32_t*)&g_al[i1] = lp;
        }
    }
    (void)dummy;
}

// ---------------------------------------------------------------------------
extern "C" void kernel_launch(void* const* d_in, const int* in_sizes, int n_in,
                              void* d_out, int out_size) {
    const float* x  = (const float*)d_in[0];
    const float* aw = (const float*)d_in[1];
    const float* ab = (const float*)d_in[2];
    const float* aA = (const float*)d_in[3];
    const float* aB = (const float*)d_in[4];
    const float* pw = (const float*)d_in[5];
    const float* pb = (const float*)d_in[6];
    const float* pA = (const float*)d_in[7];
    const float* pB = (const float*)d_in[8];
    (void)in_sizes; (void)n_in; (void)out_size;

    float* out  = (float*)d_out;
    float* outQ = out + (size_t)MM*CC;
    float* outK = out + (size_t)2*MM*CC;

    const int SMEM_GEMM  = 2 * STAGE_BYTES + 1024;          // 197632 B
    const int SMEM_FLASH = FKV_BASE + 2 * FKV_STAGE + 1024; // 99328 B -> 2 CTA/SM
    cudaFuncSetAttribute(mma_gemm<0>, cudaFuncAttributeMaxDynamicSharedMemorySize, SMEM_GEMM);
    cudaFuncSetAttribute(mma_gemm<1>, cudaFuncAttributeMaxDynamicSharedMemorySize, SMEM_GEMM);
    cudaFuncSetAttribute(flash_mma, cudaFuncAttributeMaxDynamicSharedMemorySize, SMEM_FLASH);

    // 1) bf16 hi/lo splits of x, c_attn_w, c_proj_w
    conv_split<0><<<(MM*CC/4 + 255)/256, 256>>>(x, MM*CC/4);
    conv_split<1><<<(NQKV*CC/4 + 255)/256, 256>>>(aw, NQKV*CC/4);
    conv_split<2><<<(CC*CC/4 + 255)/256, 256>>>(pw, CC*CC/4);
    // 2) LoRA intermediate for c_attn
    lora_kernel<0><<<MM/8, 256>>>(x, aA);
    // 3) QKV GEMM (HMMA): q/k/v bf16-split scatter + query/key outputs
    mma_gemm<0><<<dim3(NQKV/256, MM/128), 256, SMEM_GEMM>>>(ab, aB, outQ, outK);
    // 4) Tensor-core causal flash attention v2 -> g_y (+ bf16 split g_ah/g_al)
    flash_mma<<<dim3(TT/128, BB*HH), 128, SMEM_FLASH>>>(nullptr);
    // 5) LoRA intermediate for c_proj
    lora_kernel<1><<<MM/8, 256>>>(nullptr, pA);
    // 6) proj GEMM (HMMA) + bias + LoRA -> out
    mma_gemm<1><<<dim3(CC/256, MM/128), 256, SMEM_GEMM>>>(pb, pB, out, nullptr);
}

// round 13
// speedup vs baseline: 1.3595x; 1.3595x over previous
#include <cuda_runtime.h>
#include <cuda_fp16.h>
#include <cstdint>
#include <cstddef>

// Problem constants (fixed by the dataset)
#define BB 4
#define TT 2048
#define CC 1024
#define HH 16
#define DD 64
#define RR 8
#define MM (BB*TT)        // 8192
#define NQKV (3*CC)       // 3072

// Scratch (device globals -- referenced ONLY from device code).
__device__ float g_y[(size_t)MM*CC];         // attention output [B,T,C]
__device__ float g_t[(size_t)MM*RR];         // LoRA intermediate x@A^T
// fp16 buffers: A-side (activations) split hi/lo; B-side (weights/K/V) hi only.
__device__ __half g_ah[(size_t)MM*CC];       // x, then attention y (hi)
__device__ __half g_al[(size_t)MM*CC];       // (lo residual)
__device__ __half g_bh[(size_t)NQKV*CC];     // c_attn_w (fp16)
__device__ __half g_pwh[(size_t)CC*CC];      // c_proj_w (fp16)
// q split hi/lo (A-side of QK^T); k, v single fp16 (B-side)
__device__ __half g_qh[(size_t)BB*HH*TT*DD];
__device__ __half g_ql[(size_t)BB*HH*TT*DD];
__device__ __half g_kh[(size_t)BB*HH*TT*DD];
__device__ __half g_vh[(size_t)BB*HH*TT*DD];

// ---------------------------------------------------------------------------
// Helpers (base-target ISA only: cp.async / ldmatrix / mma.sync)
// ---------------------------------------------------------------------------
__device__ __forceinline__ uint32_t smem_u32(const void* p) {
    uint32_t a;
    asm("{ .reg .u64 t; cvta.to.shared.u64 t, %1; cvt.u32.u64 %0, t; }"
        : "=r"(a) : "l"(p));
    return a;
}
#define SWZ128(off) ((off) ^ (((off) >> 3) & 0x70))

#define CP_ASYNC16(dst, src) \
    asm volatile("cp.async.cg.shared.global [%0], [%1], 16;" :: "r"(dst), "l"(src))
#define CP_COMMIT() asm volatile("cp.async.commit_group;" ::: "memory")
#define CP_WAIT(n)  asm volatile("cp.async.wait_group %0;" :: "n"(n) : "memory")

#define LDSM_X4(r, a) \
    asm volatile("ldmatrix.sync.aligned.m8n8.x4.shared.b16 {%0,%1,%2,%3}, [%4];" \
                 : "=r"((r)[0]), "=r"((r)[1]), "=r"((r)[2]), "=r"((r)[3]) : "r"(a))
#define LDSM_X4_T(r, a) \
    asm volatile("ldmatrix.sync.aligned.m8n8.x4.trans.shared.b16 {%0,%1,%2,%3}, [%4];" \
                 : "=r"((r)[0]), "=r"((r)[1]), "=r"((r)[2]), "=r"((r)[3]) : "r"(a))

#define MMA16816(d, a, b0, b1) \
    asm volatile("mma.sync.aligned.m16n8k16.row.col.f32.f16.f16.f32 " \
                 "{%0,%1,%2,%3}, {%4,%5,%6,%7}, {%8,%9}, {%0,%1,%2,%3};" \
                 : "+f"((d)[0]), "+f"((d)[1]), "+f"((d)[2]), "+f"((d)[3]) \
                 : "r"((a)[0]), "r"((a)[1]), "r"((a)[2]), "r"((a)[3]), \
                   "r"(b0), "r"(b1))

// split a float pair into fp16 hi pair + fp16 lo (residual) pair
__device__ __forceinline__ void split_pair(float a, float b, uint32_t& hi, uint32_t& lo) {
    __half2 h = __floats2half2_rn(a, b);
    float ra = a - __half2float(__low2half(h));
    float rb = b - __half2float(__high2half(h));
    __half2 l = __floats2half2_rn(ra, rb);
    hi = *(uint32_t*)&h;
    lo = *(uint32_t*)&l;
}
__device__ __forceinline__ uint32_t pack_half2(float a, float b) {
    __half2 h = __floats2half2_rn(a, b);
    return *(uint32_t*)&h;
}

// ---------------------------------------------------------------------------
// fp32 -> fp16 conversion. DST 0: x -> g_ah/g_al (hi+lo split);
// DST 1: attn W -> g_bh (hi only); DST 2: proj W -> g_pwh (hi only).
// ---------------------------------------------------------------------------
template<int DST>
__global__ void conv_split(const float* __restrict__ src, int n4) {
    int i = blockIdx.x * blockDim.x + threadIdx.x;
    if (i >= n4) return;
    float4 v = ((const float4*)src)[i];
    if (DST == 0) {
        uint32_t h0, l0, h1, l1;
        split_pair(v.x, v.y, h0, l0);
        split_pair(v.z, v.w, h1, l1);
        ((uint32_t*)g_ah)[2*i]   = h0;
        ((uint32_t*)g_ah)[2*i+1] = h1;
        ((uint32_t*)g_al)[2*i]   = l0;
        ((uint32_t*)g_al)[2*i+1] = l1;
    } else {
        __half* H = (DST == 1) ? g_bh : g_pwh;
        ((uint32_t*)H)[2*i]   = pack_half2(v.x, v.y);
        ((uint32_t*)H)[2*i+1] = pack_half2(v.z, v.w);
    }
}

// ---------------------------------------------------------------------------
// LoRA intermediate: t[m, r] = sum_k X[m,k] * A[r,k]   (one warp per row m)
// ---------------------------------------------------------------------------
template<int SRC>
__global__ void lora_kernel(const float* __restrict__ Xin, const float* __restrict__ A) {
    const float* X = (SRC == 1) ? g_y : Xin;
    int warp = (blockIdx.x * blockDim.x + threadIdx.x) >> 5;
    int lane = threadIdx.x & 31;
    const float* xr = X + (size_t)warp * CC;
    float acc[RR];
#pragma unroll
    for (int r = 0; r < RR; r++) acc[r] = 0.f;
    for (int k = lane; k < CC; k += 32) {
        float xv = xr[k];
#pragma unroll
        for (int r = 0; r < RR; r++) acc[r] = fmaf(xv, __ldg(&A[r*CC + k]), acc[r]);
    }
#pragma unroll
    for (int r = 0; r < RR; r++) {
        acc[r] += __shfl_xor_sync(0xffffffffu, acc[r], 16);
        acc[r] += __shfl_xor_sync(0xffffffffu, acc[r], 8);
        acc[r] += __shfl_xor_sync(0xffffffffu, acc[r], 4);
        acc[r] += __shfl_xor_sync(0xffffffffu, acc[r], 2);
        acc[r] += __shfl_xor_sync(0xffffffffu, acc[r], 1);
    }
    if (lane == 0) {
#pragma unroll
        for (int r = 0; r < RR; r++) g_t[(size_t)warp*RR + r] = acc[r];
    }
}

// ---------------------------------------------------------------------------
// fp16 2-term HMMA GEMM: D = (Ah+Al)*Bh  (= A*Bh exactly; err = A*(B-Bh)).
// CTA tile 128(M) x 256(N), 256 threads: 8 warps of 64x64, term-major MMAs.
// K chunks of 64, double-buffered cp.async, stage = 64KB (A hi/lo + B), 129KB.
// MODE 0: QKV (W=g_bh) -> q hi/lo + k/v fp16 scatter + query/key fp32 outs.
// MODE 1: proj (W=g_pwh) -> plain [M,C] fp32 output.
// ---------------------------------------------------------------------------
#define STAGE_BYTES 65536
#define OFF_AH 0
#define OFF_AL 16384
#define OFF_B  32768

template<int MODE>
__global__ void __launch_bounds__(256) mma_gemm(const float* __restrict__ bias,
                                                const float* __restrict__ Blora,
                                                float* __restrict__ out0,
                                                float* __restrict__ out1)
{
    extern __shared__ char smem_raw[];
    uint32_t raw = smem_u32(smem_raw);
    uint32_t sb = (raw + 1023u) & ~1023u;

    const __half* Wh = (MODE == 0) ? g_bh : g_pwh;   // device-side select

    int tid  = threadIdx.x;
    int wid  = tid >> 5, lane = tid & 31;
    int wm   = wid >> 2;       // 0..1 -> 64-row slab
    int wn   = wid & 3;        // 0..3 -> 64-col slab
    int bm = blockIdx.y * 128;
    int bn = blockIdx.x * 256;

    int lrow = tid >> 3;       // 0..31
    int lq   = tid & 7;        // uint4 index within 128B row

    float acc[4][8][4];
#pragma unroll
    for (int i = 0; i < 4; i++)
#pragma unroll
        for (int j = 0; j < 8; j++)
#pragma unroll
            for (int c = 0; c < 4; c++) acc[i][j][c] = 0.f;

    auto load_chunk = [&](int stage, int k0) {
        uint32_t base = sb + stage * STAGE_BYTES;
#pragma unroll
        for (int i = 0; i < 4; i++) {
            int row = lrow + i * 32;
            uint32_t boff = SWZ128((uint32_t)(row * 128 + lq * 16));
            size_t go = (size_t)(bm + row) * CC + k0 + lq * 8;
            CP_ASYNC16(base + OFF_AH + boff, g_ah + go);
            CP_ASYNC16(base + OFF_AL + boff, g_al + go);
        }
#pragma unroll
        for (int i = 0; i < 8; i++) {
            int row = lrow + i * 32;
            uint32_t boff = SWZ128((uint32_t)(row * 128 + lq * 16));
            size_t go = (size_t)(bn + row) * CC + k0 + lq * 8;
            CP_ASYNC16(base + OFF_B + boff, Wh + go);
        }
        CP_COMMIT();
    };

    const int NCHUNK = CC / 64;
    load_chunk(0, 0);

    for (int ch = 0; ch < NCHUNK; ++ch) {
        if (ch + 1 < NCHUNK) {
            load_chunk((ch + 1) & 1, (ch + 1) * 64);
            CP_WAIT(1);
        } else {
            CP_WAIT(0);
        }
        __syncthreads();
        uint32_t base = sb + (ch & 1) * STAGE_BYTES;

#pragma unroll
        for (int ks = 0; ks < 4; ks++) {
            uint32_t ah[4][4], al[4][4];
#pragma unroll
            for (int ma = 0; ma < 4; ma++) {
                int row = wm * 64 + ma * 16 + (lane & 15);
                uint32_t kb = ks * 32 + ((lane >> 4) << 4);
                uint32_t off = SWZ128((uint32_t)(row * 128) + kb);
                LDSM_X4(ah[ma], base + OFF_AH + off);
                LDSM_X4(al[ma], base + OFF_AL + off);
            }
#pragma unroll
            for (int nb = 0; nb < 4; nb++) {
                uint32_t b4[4];
                int row = wn * 64 + nb * 16 + (lane & 7) + ((lane >> 4) << 3);
                uint32_t kb = ks * 32 + (((lane >> 3) & 1) << 4);
                uint32_t off = SWZ128((uint32_t)(row * 128) + kb);
                LDSM_X4(b4, base + OFF_B + off);
#pragma unroll
                for (int ma = 0; ma < 4; ma++)
#pragma unroll
                    for (int h = 0; h < 2; h++)
                        MMA16816(acc[ma][nb*2+h], ah[ma], b4[2*h], b4[2*h+1]);
#pragma unroll
                for (int ma = 0; ma < 4; ma++)
#pragma unroll
                    for (int h = 0; h < 2; h++)
                        MMA16816(acc[ma][nb*2+h], al[ma], b4[2*h], b4[2*h+1]);
            }
        }
        __syncthreads();
    }

    // ---- epilogue: + bias + LoRA, write out ----
#pragma unroll
    for (int ma = 0; ma < 4; ma++) {
        int m0 = bm + wm * 64 + ma * 16 + (lane >> 2);
        int m1 = m0 + 8;
        float4 t0a = *(const float4*)&g_t[(size_t)m0 * RR];
        float4 t0b = *(const float4*)&g_t[(size_t)m0 * RR + 4];
        float4 t1a = *(const float4*)&g_t[(size_t)m1 * RR];
        float4 t1b = *(const float4*)&g_t[(size_t)m1 * RR + 4];
#pragma unroll
        for (int na = 0; na < 8; na++) {
            int n0 = bn + wn * 64 + na * 8 + (lane & 3) * 2;
            int n1 = n0 + 1;
            float4 b0a = *(const float4*)&Blora[(size_t)n0 * RR];
            float4 b0b = *(const float4*)&Blora[(size_t)n0 * RR + 4];
            float4 b1a = *(const float4*)&Blora[(size_t)n1 * RR];
            float4 b1b = *(const float4*)&Blora[(size_t)n1 * RR + 4];
            float bs0 = __ldg(&bias[n0]), bs1 = __ldg(&bias[n1]);
            float v00 = acc[ma][na][0] + bs0
                + t0a.x*b0a.x + t0a.y*b0a.y + t0a.z*b0a.z + t0a.w*b0a.w
                + t0b.x*b0b.x + t0b.y*b0b.y + t0b.z*b0b.z + t0b.w*b0b.w;
            float v01 = acc[ma][na][1] + bs1
                + t0a.x*b1a.x + t0a.y*b1a.y + t0a.z*b1a.z + t0a.w*b1a.w
                + t0b.x*b1b.x + t0b.y*b1b.y + t0b.z*b1b.z + t0b.w*b1b.w;
            float v10 = acc[ma][na][2] + bs0
                + t1a.x*b0a.x + t1a.y*b0a.y + t1a.z*b0a.z + t1a.w*b0a.w
                + t1b.x*b0b.x + t1b.y*b0b.y + t1b.z*b0b.z + t1b.w*b0b.w;
            float v11 = acc[ma][na][3] + bs1
                + t1a.x*b1a.x + t1a.y*b1a.y + t1a.z*b1a.z + t1a.w*b1a.w
                + t1b.x*b1b.x + t1b.y*b1b.y + t1b.z*b1b.z + t1b.w*b1b.w;

            if (MODE == 0) {
                int sec = n0 >> 10;            // 0=q, 1=k, 2=v
                int cci = n0 & 1023;
                int h = cci >> 6, dd = cci & 63;
                {
                    int bi = m0 >> 11, ti = m0 & 2047;
                    size_t idx = ((size_t)((bi*HH) + h)*TT + ti)*DD + dd;
                    if (sec == 0) {
                        uint32_t hp, lp; split_pair(v00, v01, hp, lp);
                        *(uint32_t*)&g_qh[idx] = hp;
                        *(uint32_t*)&g_ql[idx] = lp;
                        float2 p; p.x = v00; p.y = v01;
                        *(float2*)&out0[(size_t)m0*CC + cci] = p;
                    } else if (sec == 1) {
                        *(uint32_t*)&g_kh[idx] = pack_half2(v00, v01);
                        float2 p; p.x = v00; p.y = v01;
                        *(float2*)&out1[(size_t)m0*CC + cci] = p;
                    } else {
                        *(uint32_t*)&g_vh[idx] = pack_half2(v00, v01);
                    }
                }
                {
                    int bi = m1 >> 11, ti = m1 & 2047;
                    size_t idx = ((size_t)((bi*HH) + h)*TT + ti)*DD + dd;
                    if (sec == 0) {
                        uint32_t hp, lp; split_pair(v10, v11, hp, lp);
                        *(uint32_t*)&g_qh[idx] = hp;
                        *(uint32_t*)&g_ql[idx] = lp;
                        float2 p; p.x = v10; p.y = v11;
                        *(float2*)&out0[(size_t)m1*CC + cci] = p;
                    } else if (sec == 1) {
                        *(uint32_t*)&g_kh[idx] = pack_half2(v10, v11);
                        float2 p; p.x = v10; p.y = v11;
                        *(float2*)&out1[(size_t)m1*CC + cci] = p;
                    } else {
                        *(uint32_t*)&g_vh[idx] = pack_half2(v10, v11);
                    }
                }
            } else {
                float2 p0; p0.x = v00; p0.y = v01;
                float2 p1; p1.x = v10; p1.y = v11;
                *(float2*)&out0[(size_t)m0*CC + n0] = p0;
                *(float2*)&out0[(size_t)m1*CC + n0] = p1;
            }
        }
    }
}

// ---------------------------------------------------------------------------
// Tensor-core causal flash attention (fp16 2-term, fp32 softmax).
// CTA: 128 Q-rows, 128 threads (4 warps x 32 rows). S=(Qh+Ql)*K, O=(Ph+Pl)*V.
// Q in smem (hi/lo planes), K/V single fp16 tiles 64x64 double-buffered.
// smem = 64.5KB -> 3 CTAs/SM.
// ---------------------------------------------------------------------------
#define FQ_H 0
#define FQ_L 16384
#define FKV_BASE 32768
#define FKV_STAGE 16384
#define FKV_KH 0
#define FKV_VH 8192

__global__ void __launch_bounds__(128) flash_mma(float* __restrict__ dummy) {
    extern __shared__ char smem_raw[];
    uint32_t raw = smem_u32(smem_raw);
    uint32_t sb = (raw + 1023u) & ~1023u;

    int bh = blockIdx.y;
    int qi = gridDim.x - 1 - (int)blockIdx.x;   // long blocks first
    int tid = threadIdx.x;
    int wid = tid >> 5, lane = tid & 31;
    int row0 = qi * 128;

    const __half* Qh = g_qh + ((size_t)bh*TT + row0) * DD;
    const __half* Ql = g_ql + ((size_t)bh*TT + row0) * DD;
    const __half* Kh = g_kh + (size_t)bh*TT*DD;
    const __half* Vh = g_vh + (size_t)bh*TT*DD;

    auto load_tile64 = [&](uint32_t dst, const __half* src) {
#pragma unroll
        for (int i = 0; i < 4; i++) {
            int e = tid + i * 128;
            int row = e >> 3, q = e & 7;
            CP_ASYNC16(dst + SWZ128((uint32_t)(row * 128 + q * 16)), src + row * 64 + q * 8);
        }
    };
    auto load_tile128 = [&](uint32_t dst, const __half* src) {
#pragma unroll
        for (int i = 0; i < 8; i++) {
            int e = tid + i * 128;
            int row = e >> 3, q = e & 7;
            CP_ASYNC16(dst + SWZ128((uint32_t)(row * 128 + q * 16)), src + row * 64 + q * 8);
        }
    };
    auto load_kv = [&](int stage, int j) {
        uint32_t base = sb + FKV_BASE + stage * FKV_STAGE;
        size_t o = (size_t)j * 64 * DD;
        load_tile64(base + FKV_KH, Kh + o);
        load_tile64(base + FKV_VH, Vh + o);
        CP_COMMIT();
    };

    load_tile128(sb + FQ_H, Qh);
    load_tile128(sb + FQ_L, Ql);
    CP_COMMIT();
    load_kv(0, 0);

    float oacc[2][8][4];
#pragma unroll
    for (int ma = 0; ma < 2; ma++)
#pragma unroll
        for (int i = 0; i < 8; i++)
#pragma unroll
            for (int c = 0; c < 4; c++) oacc[ma][i][c] = 0.f;
    float m_pr[2][2] = { { -1e30f, -1e30f }, { -1e30f, -1e30f } };
    float l_pr[2][2] = { { 0.f, 0.f }, { 0.f, 0.f } };

    int jmax = 2 * qi + 1;
    for (int j = 0; j <= jmax; ++j) {
        if (j < jmax) { load_kv((j + 1) & 1, j + 1); CP_WAIT(1); }
        else          { CP_WAIT(0); }
        __syncthreads();
        uint32_t kvb = sb + FKV_BASE + (j & 1) * FKV_STAGE;

        // ---- S = Q K^T (2-term: Qh*K + Ql*K) ----
        float sacc[2][8][4];
#pragma unroll
        for (int ma = 0; ma < 2; ma++)
#pragma unroll
            for (int i = 0; i < 8; i++)
#pragma unroll
                for (int c = 0; c < 4; c++) sacc[ma][i][c] = 0.f;
#pragma unroll
        for (int k = 0; k < 4; k++) {
            uint32_t qhf[2][4], qlf[2][4];
#pragma unroll
            for (int ma = 0; ma < 2; ma++) {
                int row = wid * 32 + ma * 16 + (lane & 15);
                uint32_t kb = k * 32 + ((lane >> 4) << 4);
                uint32_t off = SWZ128((uint32_t)(row * 128) + kb);
                LDSM_X4(qhf[ma], sb + FQ_H + off);
                LDSM_X4(qlf[ma], sb + FQ_L + off);
            }
#pragma unroll
            for (int np = 0; np < 4; np++) {
                uint32_t kh4[4];
                int row = np * 16 + (lane & 7) + ((lane >> 3) & 1) * 8;
                uint32_t col = k * 32 + ((lane >> 4) << 4);
                uint32_t off = SWZ128((uint32_t)(row * 128) + col);
                LDSM_X4(kh4, kvb + FKV_KH + off);
#pragma unroll
                for (int ma = 0; ma < 2; ma++) {
                    MMA16816(sacc[ma][2*np],   qhf[ma], kh4[0], kh4[2]);
                    MMA16816(sacc[ma][2*np+1], qhf[ma], kh4[1], kh4[3]);
                }
#pragma unroll
                for (int ma = 0; ma < 2; ma++) {
                    MMA16816(sacc[ma][2*np],   qlf[ma], kh4[0], kh4[2]);
                    MMA16816(sacc[ma][2*np+1], qlf[ma], kh4[1], kh4[3]);
                }
            }
        }

        // ---- scale + causal mask + online softmax (per ma) ----
        bool diag = (j >= 2 * qi);
#pragma unroll
        for (int ma = 0; ma < 2; ma++) {
            int rg0 = row0 + wid * 32 + ma * 16 + (lane >> 2);
            float mx[2] = { -1e30f, -1e30f };
#pragma unroll
            for (int na = 0; na < 8; na++) {
#pragma unroll
                for (int c = 0; c < 4; c++) {
                    float s = sacc[ma][na][c] * 0.125f;
                    if (diag) {
                        int colg = j * 64 + na * 8 + (lane & 3) * 2 + (c & 1);
                        int rowg = rg0 + ((c >> 1) << 3);
                        if (colg > rowg) s = -1e30f;
                    }
                    sacc[ma][na][c] = s;
                    mx[c >> 1] = fmaxf(mx[c >> 1], s);
                }
            }
#pragma unroll
            for (int h = 0; h < 2; h++) {
                mx[h] = fmaxf(mx[h], __shfl_xor_sync(0xffffffffu, mx[h], 1));
                mx[h] = fmaxf(mx[h], __shfl_xor_sync(0xffffffffu, mx[h], 2));
            }
            float m_new[2], alpha[2], lsum[2] = { 0.f, 0.f };
#pragma unroll
            for (int h = 0; h < 2; h++) {
                m_new[h] = fmaxf(m_pr[ma][h], mx[h]);
                alpha[h] = __expf(m_pr[ma][h] - m_new[h]);
                m_pr[ma][h] = m_new[h];
            }
#pragma unroll
            for (int na = 0; na < 8; na++) {
#pragma unroll
                for (int c = 0; c < 4; c++) {
                    float p = __expf(sacc[ma][na][c] - m_new[c >> 1]);
                    sacc[ma][na][c] = p;
                    lsum[c >> 1] += p;
                }
            }
#pragma unroll
            for (int h = 0; h < 2; h++) {
                lsum[h] += __shfl_xor_sync(0xffffffffu, lsum[h], 1);
                lsum[h] += __shfl_xor_sync(0xffffffffu, lsum[h], 2);
                l_pr[ma][h] = l_pr[ma][h] * alpha[h] + lsum[h];
            }
#pragma unroll
            for (int na = 0; na < 8; na++) {
                oacc[ma][na][0] *= alpha[0]; oacc[ma][na][1] *= alpha[0];
                oacc[ma][na][2] *= alpha[1]; oacc[ma][na][3] *= alpha[1];
            }
        }

        // ---- O += P V (2-term: Ph*V + Pl*V) ----
#pragma unroll
        for (int s = 0; s < 4; s++) {
            uint32_t ph[2][4], pl[2][4];
#pragma unroll
            for (int ma = 0; ma < 2; ma++) {
                split_pair(sacc[ma][2*s][0],   sacc[ma][2*s][1],   ph[ma][0], pl[ma][0]);
                split_pair(sacc[ma][2*s][2],   sacc[ma][2*s][3],   ph[ma][1], pl[ma][1]);
                split_pair(sacc[ma][2*s+1][0], sacc[ma][2*s+1][1], ph[ma][2], pl[ma][2]);
                split_pair(sacc[ma][2*s+1][2], sacc[ma][2*s+1][3], ph[ma][3], pl[ma][3]);
            }
#pragma unroll
            for (int np = 0; np < 4; np++) {
                uint32_t vh4[4];
                int row = s * 16 + (lane & 7) + ((lane >> 3) & 1) * 8;
                uint32_t col = np * 32 + ((lane >> 4) << 4);
                uint32_t off = SWZ128((uint32_t)(row * 128) + col);
                LDSM_X4_T(vh4, kvb + FKV_VH + off);
#pragma unroll
                for (int ma = 0; ma < 2; ma++) {
                    MMA16816(oacc[ma][2*np],   ph[ma], vh4[0], vh4[1]);
                    MMA16816(oacc[ma][2*np+1], ph[ma], vh4[2], vh4[3]);
                }
#pragma unroll
                for (int ma = 0; ma < 2; ma++) {
                    MMA16816(oacc[ma][2*np],   pl[ma], vh4[0], vh4[1]);
                    MMA16816(oacc[ma][2*np+1], pl[ma], vh4[2], vh4[3]);
                }
            }
        }
        __syncthreads();
    }

    // ---- epilogue: normalize, write fp32 g_y + fp16 split g_ah/g_al ----
    int h = bh & (HH - 1), bi = bh >> 4;
#pragma unroll
    for (int ma = 0; ma < 2; ma++) {
        float inv0 = 1.0f / l_pr[ma][0];
        float inv1 = 1.0f / l_pr[ma][1];
        int t0 = row0 + wid * 32 + ma * 16 + (lane >> 2);
        int t1 = t0 + 8;
        int dbase = h * DD + (lane & 3) * 2;
#pragma unroll
        for (int na = 0; na < 8; na++) {
            int d = dbase + na * 8;
            size_t i0 = ((size_t)(bi*TT + t0))*CC + d;
            size_t i1 = ((size_t)(bi*TT + t1))*CC + d;
            float v00 = oacc[ma][na][0]*inv0, v01 = oacc[ma][na][1]*inv0;
            float v10 = oacc[ma][na][2]*inv1, v11 = oacc[ma][na][3]*inv1;
            float2 p0; p0.x = v00; p0.y = v01;
            float2 p1; p1.x = v10; p1.y = v11;
            *(float2*)&g_y[i0] = p0;
            *(float2*)&g_y[i1] = p1;
            uint32_t hp, lp;
            split_pair(v00, v01, hp, lp);
            *(uint32_t*)&g_ah[i0] = hp; *(uint32_t*)&g_al[i0] = lp;
            split_pair(v10, v11, hp, lp);
            *(uint32_t*)&g_ah[i1] = hp; *(uint32_t*)&g_al[i1] = lp;
        }
    }
    (void)dummy;
}

// ---------------------------------------------------------------------------
extern "C" void kernel_launch(void* const* d_in, const int* in_sizes, int n_in,
                              void* d_out, int out_size) {
    const float* x  = (const float*)d_in[0];
    const float* aw = (const float*)d_in[1];
    const float* ab = (const float*)d_in[2];
    const float* aA = (const float*)d_in[3];
    const float* aB = (const float*)d_in[4];
    const float* pw = (const float*)d_in[5];
    const float* pb = (const float*)d_in[6];
    const float* pA = (const float*)d_in[7];
    const float* pB = (const float*)d_in[8];
    (void)in_sizes; (void)n_in; (void)out_size;

    float* out  = (float*)d_out;
    float* outQ = out + (size_t)MM*CC;
    float* outK = out + (size_t)2*MM*CC;

    const int SMEM_GEMM  = 2 * STAGE_BYTES + 1024;          // 132096 B (proven)
    const int SMEM_FLASH = FKV_BASE + 2 * FKV_STAGE + 1024; // 66560 B -> 3 CTA/SM
    cudaFuncSetAttribute(mma_gemm<0>, cudaFuncAttributeMaxDynamicSharedMemorySize, SMEM_GEMM);
    cudaFuncSetAttribute(mma_gemm<1>, cudaFuncAttributeMaxDynamicSharedMemorySize, SMEM_GEMM);
    cudaFuncSetAttribute(flash_mma, cudaFuncAttributeMaxDynamicSharedMemorySize, SMEM_FLASH);

    // 1) fp16 conversions: x (hi/lo), c_attn_w (hi), c_proj_w (hi)
    conv_split<0><<<(MM*CC/4 + 255)/256, 256>>>(x, MM*CC/4);
    conv_split<1><<<(NQKV*CC/4 + 255)/256, 256>>>(aw, NQKV*CC/4);
    conv_split<2><<<(CC*CC/4 + 255)/256, 256>>>(pw, CC*CC/4);
    // 2) LoRA intermediate for c_attn
    lora_kernel<0><<<MM/8, 256>>>(x, aA);
    // 3) QKV GEMM (HMMA fp16 2-term): q hi/lo + k/v scatter + query/key outs
    mma_gemm<0><<<dim3(NQKV/256, MM/128), 256, SMEM_GEMM>>>(ab, aB, outQ, outK);
    // 4) Causal flash attention (fp16 2-term) -> g_y (+ fp16 split g_ah/g_al)
    flash_mma<<<dim3(TT/128, BB*HH), 128, SMEM_FLASH>>>(nullptr);
    // 5) LoRA intermediate for c_proj
    lora_kernel<1><<<MM/8, 256>>>(nullptr, pA);
    // 6) proj GEMM (HMMA fp16 2-term) + bias + LoRA -> out
    mma_gemm<1><<<dim3(CC/256, MM/128), 256, SMEM_GEMM>>>(pb, pB, out, nullptr);
}

// round 14
// speedup vs baseline: 1.5574x; 1.1456x over previous
#include <cuda_runtime.h>
#include <cuda_fp16.h>
#include <cstdint>
#include <cstddef>

// Problem constants (fixed by the dataset)
#define BB 4
#define TT 2048
#define CC 1024
#define HH 16
#define DD 64
#define RR 8
#define MM (BB*TT)        // 8192
#define NQKV (3*CC)       // 3072

// Scratch (device globals -- referenced ONLY from device code).
__device__ float g_t[(size_t)MM*RR];         // LoRA intermediate
__device__ __half g_ah[(size_t)MM*CC];       // x (hi), then attention y (fp16)
__device__ __half g_al[(size_t)MM*CC];       // x lo residual (QKV GEMM only)
__device__ __half g_bh[(size_t)NQKV*CC];     // c_attn_w (fp16)
__device__ __half g_pwh[(size_t)CC*CC];      // c_proj_w (fp16)
// q split hi/lo (A-side of QK^T); k, v single fp16 (B-side)
__device__ __half g_qh[(size_t)BB*HH*TT*DD];
__device__ __half g_ql[(size_t)BB*HH*TT*DD];
__device__ __half g_kh[(size_t)BB*HH*TT*DD];
__device__ __half g_vh[(size_t)BB*HH*TT*DD];

// ---------------------------------------------------------------------------
// Helpers (base-target ISA only: cp.async / ldmatrix / mma.sync)
// ---------------------------------------------------------------------------
__device__ __forceinline__ uint32_t smem_u32(const void* p) {
    uint32_t a;
    asm("{ .reg .u64 t; cvta.to.shared.u64 t, %1; cvt.u32.u64 %0, t; }"
        : "=r"(a) : "l"(p));
    return a;
}
#define SWZ128(off) ((off) ^ (((off) >> 3) & 0x70))

#define CP_ASYNC16(dst, src) \
    asm volatile("cp.async.cg.shared.global [%0], [%1], 16;" :: "r"(dst), "l"(src))
#define CP_COMMIT() asm volatile("cp.async.commit_group;" ::: "memory")
#define CP_WAIT(n)  asm volatile("cp.async.wait_group %0;" :: "n"(n) : "memory")

#define LDSM_X4(r, a) \
    asm volatile("ldmatrix.sync.aligned.m8n8.x4.shared.b16 {%0,%1,%2,%3}, [%4];" \
                 : "=r"((r)[0]), "=r"((r)[1]), "=r"((r)[2]), "=r"((r)[3]) : "r"(a))
#define LDSM_X4_T(r, a) \
    asm volatile("ldmatrix.sync.aligned.m8n8.x4.trans.shared.b16 {%0,%1,%2,%3}, [%4];" \
                 : "=r"((r)[0]), "=r"((r)[1]), "=r"((r)[2]), "=r"((r)[3]) : "r"(a))

#define MMA16816(d, a, b0, b1) \
    asm volatile("mma.sync.aligned.m16n8k16.row.col.f32.f16.f16.f32 " \
                 "{%0,%1,%2,%3}, {%4,%5,%6,%7}, {%8,%9}, {%0,%1,%2,%3};" \
                 : "+f"((d)[0]), "+f"((d)[1]), "+f"((d)[2]), "+f"((d)[3]) \
                 : "r"((a)[0]), "r"((a)[1]), "r"((a)[2]), "r"((a)[3]), \
                   "r"(b0), "r"(b1))

// split a float pair into fp16 hi pair + fp16 lo (residual) pair
__device__ __forceinline__ void split_pair(float a, float b, uint32_t& hi, uint32_t& lo) {
    __half2 h = __floats2half2_rn(a, b);
    float ra = a - __half2float(__low2half(h));
    float rb = b - __half2float(__high2half(h));
    __half2 l = __floats2half2_rn(ra, rb);
    hi = *(uint32_t*)&h;
    lo = *(uint32_t*)&l;
}
__device__ __forceinline__ uint32_t pack_half2(float a, float b) {
    __half2 h = __floats2half2_rn(a, b);
    return *(uint32_t*)&h;
}

// ---------------------------------------------------------------------------
// fp32 -> fp16 conversion. DST 0: x -> g_ah/g_al (hi+lo split);
// DST 1: attn W -> g_bh (hi only); DST 2: proj W -> g_pwh (hi only).
// ---------------------------------------------------------------------------
template<int DST>
__global__ void conv_split(const float* __restrict__ src, int n4) {
    int i = blockIdx.x * blockDim.x + threadIdx.x;
    if (i >= n4) return;
    float4 v = ((const float4*)src)[i];
    if (DST == 0) {
        uint32_t h0, l0, h1, l1;
        split_pair(v.x, v.y, h0, l0);
        split_pair(v.z, v.w, h1, l1);
        ((uint32_t*)g_ah)[2*i]   = h0;
        ((uint32_t*)g_ah)[2*i+1] = h1;
        ((uint32_t*)g_al)[2*i]   = l0;
        ((uint32_t*)g_al)[2*i+1] = l1;
    } else {
        __half* H = (DST == 1) ? g_bh : g_pwh;
        ((uint32_t*)H)[2*i]   = pack_half2(v.x, v.y);
        ((uint32_t*)H)[2*i+1] = pack_half2(v.z, v.w);
    }
}

// ---------------------------------------------------------------------------
// LoRA intermediate from fp32 x: t[m,r] = sum_k x[m,k]*A[r,k]
// ---------------------------------------------------------------------------
__global__ void lora_kernel_f(const float* __restrict__ X, const float* __restrict__ A) {
    int warp = (blockIdx.x * blockDim.x + threadIdx.x) >> 5;
    int lane = threadIdx.x & 31;
    const float* xr = X + (size_t)warp * CC;
    float acc[RR];
#pragma unroll
    for (int r = 0; r < RR; r++) acc[r] = 0.f;
    for (int k = lane; k < CC; k += 32) {
        float xv = xr[k];
#pragma unroll
        for (int r = 0; r < RR; r++) acc[r] = fmaf(xv, __ldg(&A[r*CC + k]), acc[r]);
    }
#pragma unroll
    for (int r = 0; r < RR; r++) {
        acc[r] += __shfl_xor_sync(0xffffffffu, acc[r], 16);
        acc[r] += __shfl_xor_sync(0xffffffffu, acc[r], 8);
        acc[r] += __shfl_xor_sync(0xffffffffu, acc[r], 4);
        acc[r] += __shfl_xor_sync(0xffffffffu, acc[r], 2);
        acc[r] += __shfl_xor_sync(0xffffffffu, acc[r], 1);
    }
    if (lane == 0) {
#pragma unroll
        for (int r = 0; r < RR; r++) g_t[(size_t)warp*RR + r] = acc[r];
    }
}

// LoRA intermediate from fp16 attention output g_ah (y).
__global__ void lora_kernel_h(const float* __restrict__ A) {
    int warp = (blockIdx.x * blockDim.x + threadIdx.x) >> 5;
    int lane = threadIdx.x & 31;
    const __half* xr = g_ah + (size_t)warp * CC;
    float acc[RR];
#pragma unroll
    for (int r = 0; r < RR; r++) acc[r] = 0.f;
    for (int k2 = lane; k2 < CC/2; k2 += 32) {
        __half2 xv2 = ((const __half2*)xr)[k2];
        float x0 = __half2float(__low2half(xv2));
        float x1 = __half2float(__high2half(xv2));
#pragma unroll
        for (int r = 0; r < RR; r++) {
            acc[r] = fmaf(x0, __ldg(&A[r*CC + 2*k2]),     acc[r]);
            acc[r] = fmaf(x1, __ldg(&A[r*CC + 2*k2 + 1]), acc[r]);
        }
    }
#pragma unroll
    for (int r = 0; r < RR; r++) {
        acc[r] += __shfl_xor_sync(0xffffffffu, acc[r], 16);
        acc[r] += __shfl_xor_sync(0xffffffffu, acc[r], 8);
        acc[r] += __shfl_xor_sync(0xffffffffu, acc[r], 4);
        acc[r] += __shfl_xor_sync(0xffffffffu, acc[r], 2);
        acc[r] += __shfl_xor_sync(0xffffffffu, acc[r], 1);
    }
    if (lane == 0) {
#pragma unroll
        for (int r = 0; r < RR; r++) g_t[(size_t)warp*RR + r] = acc[r];
    }
}

// ---------------------------------------------------------------------------
// fp16 HMMA GEMM + bias + rank-8 LoRA epilogue.
// CTA tile 128(M) x 256(N), 256 threads: 8 warps of 64x64, term-major MMAs.
// MODE 0 (QKV): 2-term (Ah+Al)*Bh, stage 64KB (1 CTA/SM).
//   -> q hi/lo + k/v fp16 scatter + query/key fp32 outputs.
// MODE 1 (proj): 1-term Ah*Bh, stage 48KB (2 CTAs/SM) -> [M,C] fp32 output.
// ---------------------------------------------------------------------------
template<int MODE>
__global__ void __launch_bounds__(256) mma_gemm(const float* __restrict__ bias,
                                                const float* __restrict__ Blora,
                                                float* __restrict__ out0,
                                                float* __restrict__ out1)
{
    constexpr int TERMS = (MODE == 0) ? 2 : 1;
    constexpr uint32_t ST_BYTES = (MODE == 0) ? 65536u : 49152u;
    constexpr uint32_t OFF_AH = 0;
    constexpr uint32_t OFF_AL = 16384;                       // MODE 0 only
    constexpr uint32_t OFF_B  = (MODE == 0) ? 32768u : 16384u;

    extern __shared__ char smem_raw[];
    uint32_t raw = smem_u32(smem_raw);
    uint32_t sb = (raw + 1023u) & ~1023u;

    const __half* Wh = (MODE == 0) ? g_bh : g_pwh;

    int tid  = threadIdx.x;
    int wid  = tid >> 5, lane = tid & 31;
    int wm   = wid >> 2;
    int wn   = wid & 3;
    int bm = blockIdx.y * 128;
    int bn = blockIdx.x * 256;

    int lrow = tid >> 3;
    int lq   = tid & 7;

    float acc[4][8][4];
#pragma unroll
    for (int i = 0; i < 4; i++)
#pragma unroll
        for (int j = 0; j < 8; j++)
#pragma unroll
            for (int c = 0; c < 4; c++) acc[i][j][c] = 0.f;

    auto load_chunk = [&](int stage, int k0) {
        uint32_t base = sb + stage * ST_BYTES;
#pragma unroll
        for (int i = 0; i < 4; i++) {
            int row = lrow + i * 32;
            uint32_t boff = SWZ128((uint32_t)(row * 128 + lq * 16));
            size_t go = (size_t)(bm + row) * CC + k0 + lq * 8;
            CP_ASYNC16(base + OFF_AH + boff, g_ah + go);
            if (TERMS == 2) CP_ASYNC16(base + OFF_AL + boff, g_al + go);
        }
#pragma unroll
        for (int i = 0; i < 8; i++) {
            int row = lrow + i * 32;
            uint32_t boff = SWZ128((uint32_t)(row * 128 + lq * 16));
            size_t go = (size_t)(bn + row) * CC + k0 + lq * 8;
            CP_ASYNC16(base + OFF_B + boff, Wh + go);
        }
        CP_COMMIT();
    };

    const int NCHUNK = CC / 64;
    load_chunk(0, 0);

    for (int ch = 0; ch < NCHUNK; ++ch) {
        if (ch + 1 < NCHUNK) {
            load_chunk((ch + 1) & 1, (ch + 1) * 64);
            CP_WAIT(1);
        } else {
            CP_WAIT(0);
        }
        __syncthreads();
        uint32_t base = sb + (ch & 1) * ST_BYTES;

#pragma unroll
        for (int ks = 0; ks < 4; ks++) {
            uint32_t ah[4][4], al[4][4];
#pragma unroll
            for (int ma = 0; ma < 4; ma++) {
                int row = wm * 64 + ma * 16 + (lane & 15);
                uint32_t kb = ks * 32 + ((lane >> 4) << 4);
                uint32_t off = SWZ128((uint32_t)(row * 128) + kb);
                LDSM_X4(ah[ma], base + OFF_AH + off);
                if (TERMS == 2) LDSM_X4(al[ma], base + OFF_AL + off);
            }
#pragma unroll
            for (int nb = 0; nb < 4; nb++) {
                uint32_t b4[4];
                int row = wn * 64 + nb * 16 + (lane & 7) + ((lane >> 4) << 3);
                uint32_t kb = ks * 32 + (((lane >> 3) & 1) << 4);
                uint32_t off = SWZ128((uint32_t)(row * 128) + kb);
                LDSM_X4(b4, base + OFF_B + off);
#pragma unroll
                for (int ma = 0; ma < 4; ma++)
#pragma unroll
                    for (int h = 0; h < 2; h++)
                        MMA16816(acc[ma][nb*2+h], ah[ma], b4[2*h], b4[2*h+1]);
                if (TERMS == 2) {
#pragma unroll
                    for (int ma = 0; ma < 4; ma++)
#pragma unroll
                        for (int h = 0; h < 2; h++)
                            MMA16816(acc[ma][nb*2+h], al[ma], b4[2*h], b4[2*h+1]);
                }
            }
        }
        __syncthreads();
    }

    // ---- epilogue: + bias + LoRA, write out ----
#pragma unroll
    for (int ma = 0; ma < 4; ma++) {
        int m0 = bm + wm * 64 + ma * 16 + (lane >> 2);
        int m1 = m0 + 8;
        float4 t0a = *(const float4*)&g_t[(size_t)m0 * RR];
        float4 t0b = *(const float4*)&g_t[(size_t)m0 * RR + 4];
        float4 t1a = *(const float4*)&g_t[(size_t)m1 * RR];
        float4 t1b = *(const float4*)&g_t[(size_t)m1 * RR + 4];
#pragma unroll
        for (int na = 0; na < 8; na++) {
            int n0 = bn + wn * 64 + na * 8 + (lane & 3) * 2;
            int n1 = n0 + 1;
            float4 b0a = *(const float4*)&Blora[(size_t)n0 * RR];
            float4 b0b = *(const float4*)&Blora[(size_t)n0 * RR + 4];
            float4 b1a = *(const float4*)&Blora[(size_t)n1 * RR];
            float4 b1b = *(const float4*)&Blora[(size_t)n1 * RR + 4];
            float bs0 = __ldg(&bias[n0]), bs1 = __ldg(&bias[n1]);
            float v00 = acc[ma][na][0] + bs0
                + t0a.x*b0a.x + t0a.y*b0a.y + t0a.z*b0a.z + t0a.w*b0a.w
                + t0b.x*b0b.x + t0b.y*b0b.y + t0b.z*b0b.z + t0b.w*b0b.w;
            float v01 = acc[ma][na][1] + bs1
                + t0a.x*b1a.x + t0a.y*b1a.y + t0a.z*b1a.z + t0a.w*b1a.w
                + t0b.x*b1b.x + t0b.y*b1b.y + t0b.z*b1b.z + t0b.w*b1b.w;
            float v10 = acc[ma][na][2] + bs0
                + t1a.x*b0a.x + t1a.y*b0a.y + t1a.z*b0a.z + t1a.w*b0a.w
                + t1b.x*b0b.x + t1b.y*b0b.y + t1b.z*b0b.z + t1b.w*b0b.w;
            float v11 = acc[ma][na][3] + bs1
                + t1a.x*b1a.x + t1a.y*b1a.y + t1a.z*b1a.z + t1a.w*b1a.w
                + t1b.x*b1b.x + t1b.y*b1b.y + t1b.z*b1b.z + t1b.w*b1b.w;

            if (MODE == 0) {
                int sec = n0 >> 10;            // 0=q, 1=k, 2=v
                int cci = n0 & 1023;
                int h = cci >> 6, dd = cci & 63;
                {
                    int bi = m0 >> 11, ti = m0 & 2047;
                    size_t idx = ((size_t)((bi*HH) + h)*TT + ti)*DD + dd;
                    if (sec == 0) {
                        uint32_t hp, lp; split_pair(v00, v01, hp, lp);
                        *(uint32_t*)&g_qh[idx] = hp;
                        *(uint32_t*)&g_ql[idx] = lp;
                        float2 p; p.x = v00; p.y = v01;
                        *(float2*)&out0[(size_t)m0*CC + cci] = p;
                    } else if (sec == 1) {
                        *(uint32_t*)&g_kh[idx] = pack_half2(v00, v01);
                        float2 p; p.x = v00; p.y = v01;
                        *(float2*)&out1[(size_t)m0*CC + cci] = p;
                    } else {
                        *(uint32_t*)&g_vh[idx] = pack_half2(v00, v01);
                    }
                }
                {
                    int bi = m1 >> 11, ti = m1 & 2047;
                    size_t idx = ((size_t)((bi*HH) + h)*TT + ti)*DD + dd;
                    if (sec == 0) {
                        uint32_t hp, lp; split_pair(v10, v11, hp, lp);
                        *(uint32_t*)&g_qh[idx] = hp;
                        *(uint32_t*)&g_ql[idx] = lp;
                        float2 p; p.x = v10; p.y = v11;
                        *(float2*)&out0[(size_t)m1*CC + cci] = p;
                    } else if (sec == 1) {
                        *(uint32_t*)&g_kh[idx] = pack_half2(v10, v11);
                        float2 p; p.x = v10; p.y = v11;
                        *(float2*)&out1[(size_t)m1*CC + cci] = p;
                    } else {
                        *(uint32_t*)&g_vh[idx] = pack_half2(v10, v11);
                    }
                }
            } else {
                float2 p0; p0.x = v00; p0.y = v01;
                float2 p1; p1.x = v10; p1.y = v11;
                *(float2*)&out0[(size_t)m0*CC + n0] = p0;
                *(float2*)&out0[(size_t)m1*CC + n0] = p1;
            }
        }
    }
}

// ---------------------------------------------------------------------------
// Tensor-core causal flash attention (fp16, fp32 softmax).
// CTA: 128 Q-rows, 128 threads (4 warps x 32 rows).
// S = (Qh+Ql)*K (2-term; score errors amplify), O = Ph*V (1-term; P in [0,1]).
// Q in smem (hi/lo planes), K/V single fp16 tiles 64x64 double-buffered.
// Epilogue writes fp16 y directly to g_ah (proj GEMM A operand).
// ---------------------------------------------------------------------------
#define FQ_H 0
#define FQ_L 16384
#define FKV_BASE 32768
#define FKV_STAGE 16384
#define FKV_KH 0
#define FKV_VH 8192

__global__ void __launch_bounds__(128) flash_mma(float* __restrict__ dummy) {
    extern __shared__ char smem_raw[];
    uint32_t raw = smem_u32(smem_raw);
    uint32_t sb = (raw + 1023u) & ~1023u;

    int bh = blockIdx.y;
    int qi = gridDim.x - 1 - (int)blockIdx.x;   // long blocks first
    int tid = threadIdx.x;
    int wid = tid >> 5, lane = tid & 31;
    int row0 = qi * 128;

    const __half* Qh = g_qh + ((size_t)bh*TT + row0) * DD;
    const __half* Ql = g_ql + ((size_t)bh*TT + row0) * DD;
    const __half* Kh = g_kh + (size_t)bh*TT*DD;
    const __half* Vh = g_vh + (size_t)bh*TT*DD;

    auto load_tile64 = [&](uint32_t dst, const __half* src) {
#pragma unroll
        for (int i = 0; i < 4; i++) {
            int e = tid + i * 128;
            int row = e >> 3, q = e & 7;
            CP_ASYNC16(dst + SWZ128((uint32_t)(row * 128 + q * 16)), src + row * 64 + q * 8);
        }
    };
    auto load_tile128 = [&](uint32_t dst, const __half* src) {
#pragma unroll
        for (int i = 0; i < 8; i++) {
            int e = tid + i * 128;
            int row = e >> 3, q = e & 7;
            CP_ASYNC16(dst + SWZ128((uint32_t)(row * 128 + q * 16)), src + row * 64 + q * 8);
        }
    };
    auto load_kv = [&](int stage, int j) {
        uint32_t base = sb + FKV_BASE + stage * FKV_STAGE;
        size_t o = (size_t)j * 64 * DD;
        load_tile64(base + FKV_KH, Kh + o);
        load_tile64(base + FKV_VH, Vh + o);
        CP_COMMIT();
    };

    load_tile128(sb + FQ_H, Qh);
    load_tile128(sb + FQ_L, Ql);
    CP_COMMIT();
    load_kv(0, 0);

    float oacc[2][8][4];
#pragma unroll
    for (int ma = 0; ma < 2; ma++)
#pragma unroll
        for (int i = 0; i < 8; i++)
#pragma unroll
            for (int c = 0; c < 4; c++) oacc[ma][i][c] = 0.f;
    float m_pr[2][2] = { { -1e30f, -1e30f }, { -1e30f, -1e30f } };
    float l_pr[2][2] = { { 0.f, 0.f }, { 0.f, 0.f } };

    int jmax = 2 * qi + 1;
    for (int j = 0; j <= jmax; ++j) {
        if (j < jmax) { load_kv((j + 1) & 1, j + 1); CP_WAIT(1); }
        else          { CP_WAIT(0); }
        __syncthreads();
        uint32_t kvb = sb + FKV_BASE + (j & 1) * FKV_STAGE;

        // ---- S = Q K^T (2-term: Qh*K + Ql*K) ----
        float sacc[2][8][4];
#pragma unroll
        for (int ma = 0; ma < 2; ma++)
#pragma unroll
            for (int i = 0; i < 8; i++)
#pragma unroll
                for (int c = 0; c < 4; c++) sacc[ma][i][c] = 0.f;
#pragma unroll
        for (int k = 0; k < 4; k++) {
            uint32_t qhf[2][4], qlf[2][4];
#pragma unroll
            for (int ma = 0; ma < 2; ma++) {
                int row = wid * 32 + ma * 16 + (lane & 15);
                uint32_t kb = k * 32 + ((lane >> 4) << 4);
                uint32_t off = SWZ128((uint32_t)(row * 128) + kb);
                LDSM_X4(qhf[ma], sb + FQ_H + off);
                LDSM_X4(qlf[ma], sb + FQ_L + off);
            }
#pragma unroll
            for (int np = 0; np < 4; np++) {
                uint32_t kh4[4];
                int row = np * 16 + (lane & 7) + ((lane >> 3) & 1) * 8;
                uint32_t col = k * 32 + ((lane >> 4) << 4);
                uint32_t off = SWZ128((uint32_t)(row * 128) + col);
                LDSM_X4(kh4, kvb + FKV_KH + off);
#pragma unroll
                for (int ma = 0; ma < 2; ma++) {
                    MMA16816(sacc[ma][2*np],   qhf[ma], kh4[0], kh4[2]);
                    MMA16816(sacc[ma][2*np+1], qhf[ma], kh4[1], kh4[3]);
                }
#pragma unroll
                for (int ma = 0; ma < 2; ma++) {
                    MMA16816(sacc[ma][2*np],   qlf[ma], kh4[0], kh4[2]);
                    MMA16816(sacc[ma][2*np+1], qlf[ma], kh4[1], kh4[3]);
                }
            }
        }

        // ---- scale + causal mask + online softmax (per ma) ----
        bool diag = (j >= 2 * qi);
#pragma unroll
        for (int ma = 0; ma < 2; ma++) {
            int rg0 = row0 + wid * 32 + ma * 16 + (lane >> 2);
            float mx[2] = { -1e30f, -1e30f };
#pragma unroll
            for (int na = 0; na < 8; na++) {
#pragma unroll
                for (int c = 0; c < 4; c++) {
                    float s = sacc[ma][na][c] * 0.125f;
                    if (diag) {
                        int colg = j * 64 + na * 8 + (lane & 3) * 2 + (c & 1);
                        int rowg = rg0 + ((c >> 1) << 3);
                        if (colg > rowg) s = -1e30f;
                    }
                    sacc[ma][na][c] = s;
                    mx[c >> 1] = fmaxf(mx[c >> 1], s);
                }
            }
#pragma unroll
            for (int h = 0; h < 2; h++) {
                mx[h] = fmaxf(mx[h], __shfl_xor_sync(0xffffffffu, mx[h], 1));
                mx[h] = fmaxf(mx[h], __shfl_xor_sync(0xffffffffu, mx[h], 2));
            }
            float m_new[2], alpha[2], lsum[2] = { 0.f, 0.f };
#pragma unroll
            for (int h = 0; h < 2; h++) {
                m_new[h] = fmaxf(m_pr[ma][h], mx[h]);
                alpha[h] = __expf(m_pr[ma][h] - m_new[h]);
                m_pr[ma][h] = m_new[h];
            }
#pragma unroll
            for (int na = 0; na < 8; na++) {
#pragma unroll
                for (int c = 0; c < 4; c++) {
                    float p = __expf(sacc[ma][na][c] - m_new[c >> 1]);
                    sacc[ma][na][c] = p;
                    lsum[c >> 1] += p;
                }
            }
#pragma unroll
            for (int h = 0; h < 2; h++) {
                lsum[h] += __shfl_xor_sync(0xffffffffu, lsum[h], 1);
                lsum[h] += __shfl_xor_sync(0xffffffffu, lsum[h], 2);
                l_pr[ma][h] = l_pr[ma][h] * alpha[h] + lsum[h];
            }
#pragma unroll
            for (int na = 0; na < 8; na++) {
                oacc[ma][na][0] *= alpha[0]; oacc[ma][na][1] *= alpha[0];
                oacc[ma][na][2] *= alpha[1]; oacc[ma][na][3] *= alpha[1];
            }
        }

        // ---- O += P V (1-term: Ph*V; P in [0,1], error not amplified) ----
#pragma unroll
        for (int s = 0; s < 4; s++) {
            uint32_t ph[2][4];
#pragma unroll
            for (int ma = 0; ma < 2; ma++) {
                ph[ma][0] = pack_half2(sacc[ma][2*s][0],   sacc[ma][2*s][1]);
                ph[ma][1] = pack_half2(sacc[ma][2*s][2],   sacc[ma][2*s][3]);
                ph[ma][2] = pack_half2(sacc[ma][2*s+1][0], sacc[ma][2*s+1][1]);
                ph[ma][3] = pack_half2(sacc[ma][2*s+1][2], sacc[ma][2*s+1][3]);
            }
#pragma unroll
            for (int np = 0; np < 4; np++) {
                uint32_t vh4[4];
                int row = s * 16 + (lane & 7) + ((lane >> 3) & 1) * 8;
                uint32_t col = np * 32 + ((lane >> 4) << 4);
                uint32_t off = SWZ128((uint32_t)(row * 128) + col);
                LDSM_X4_T(vh4, kvb + FKV_VH + off);
#pragma unroll
                for (int ma = 0; ma < 2; ma++) {
                    MMA16816(oacc[ma][2*np],   ph[ma], vh4[0], vh4[1]);
                    MMA16816(oacc[ma][2*np+1], ph[ma], vh4[2], vh4[3]);
                }
            }
        }
        __syncthreads();
    }

    // ---- epilogue: normalize, write fp16 y -> g_ah ----
    int h = bh & (HH - 1), bi = bh >> 4;
#pragma unroll
    for (int ma = 0; ma < 2; ma++) {
        float inv0 = 1.0f / l_pr[ma][0];
        float inv1 = 1.0f / l_pr[ma][1];
        int t0 = row0 + wid * 32 + ma * 16 + (lane >> 2);
        int t1 = t0 + 8;
        int dbase = h * DD + (lane & 3) * 2;
#pragma unroll
        for (int na = 0; na < 8; na++) {
            int d = dbase + na * 8;
            size_t i0 = ((size_t)(bi*TT + t0))*CC + d;
            size_t i1 = ((size_t)(bi*TT + t1))*CC + d;
            *(uint32_t*)&g_ah[i0] = pack_half2(oacc[ma][na][0]*inv0, oacc[ma][na][1]*inv0);
            *(uint32_t*)&g_ah[i1] = pack_half2(oacc[ma][na][2]*inv1, oacc[ma][na][3]*inv1);
        }
    }
    (void)dummy;
}

// ---------------------------------------------------------------------------
extern "C" void kernel_launch(void* const* d_in, const int* in_sizes, int n_in,
                              void* d_out, int out_size) {
    const float* x  = (const float*)d_in[0];
    const float* aw = (const float*)d_in[1];
    const float* ab = (const float*)d_in[2];
    const float* aA = (const float*)d_in[3];
    const float* aB = (const float*)d_in[4];
    const float* pw = (const float*)d_in[5];
    const float* pb = (const float*)d_in[6];
    const float* pA = (const float*)d_in[7];
    const float* pB = (const float*)d_in[8];
    (void)in_sizes; (void)n_in; (void)out_size;

    float* out  = (float*)d_out;
    float* outQ = out + (size_t)MM*CC;
    float* outK = out + (size_t)2*MM*CC;

    const int SMEM_G0 = 2 * 65536 + 1024;   // 132096 B (1 CTA/SM)
    const int SMEM_G1 = 2 * 49152 + 1024;   // 99328 B  (2 CTAs/SM)
    const int SMEM_FL = FKV_BASE + 2 * FKV_STAGE + 1024;  // 66560 B (3 CTAs/SM)
    cudaFuncSetAttribute(mma_gemm<0>, cudaFuncAttributeMaxDynamicSharedMemorySize, SMEM_G0);
    cudaFuncSetAttribute(mma_gemm<1>, cudaFuncAttributeMaxDynamicSharedMemorySize, SMEM_G1);
    cudaFuncSetAttribute(flash_mma, cudaFuncAttributeMaxDynamicSharedMemorySize, SMEM_FL);

    // 1) fp16 conversions: x (hi/lo), c_attn_w (hi), c_proj_w (hi)
    conv_split<0><<<(MM*CC/4 + 255)/256, 256>>>(x, MM*CC/4);
    conv_split<1><<<(NQKV*CC/4 + 255)/256, 256>>>(aw, NQKV*CC/4);
    conv_split<2><<<(CC*CC/4 + 255)/256, 256>>>(pw, CC*CC/4);
    // 2) LoRA intermediate for c_attn (from fp32 x)
    lora_kernel_f<<<MM/8, 256>>>(x, aA);
    // 3) QKV GEMM (fp16 2-term): q hi/lo + k/v scatter + query/key outputs
    mma_gemm<0><<<dim3(NQKV/256, MM/128), 256, SMEM_G0>>>(ab, aB, outQ, outK);
    // 4) Causal flash attention (S 2-term, PV 1-term) -> fp16 y in g_ah
    flash_mma<<<dim3(TT/128, BB*HH), 128, SMEM_FL>>>(nullptr);
    // 5) LoRA intermediate for c_proj (from fp16 y)
    lora_kernel_h<<<MM/8, 256>>>(pA);
    // 6) proj GEMM (fp16 1-term) + bias + LoRA -> out
    mma_gemm<1><<<dim3(CC/256, MM/128), 256, SMEM_G1>>>(pb, pB, out, nullptr);
}

// round 15
// speedup vs baseline: 1.9237x; 1.2352x over previous
#include <cuda_runtime.h>
#include <cuda_fp16.h>
#include <cstdint>
#include <cstddef>

// Problem constants (fixed by the dataset)
#define BB 4
#define TT 2048
#define CC 1024
#define HH 16
#define DD 64
#define RR 8
#define MM (BB*TT)        // 8192
#define NQKV (3*CC)       // 3072

// Scratch (device globals -- referenced ONLY from device code).
__device__ float g_t[(size_t)MM*RR];         // LoRA intermediate
__device__ __half g_ah[(size_t)MM*CC];       // x (fp16), then attention y (fp16)
__device__ __half g_bh[(size_t)NQKV*CC];     // c_attn_w (fp16)
__device__ __half g_pwh[(size_t)CC*CC];      // c_proj_w (fp16)
// q split hi/lo (A-side of QK^T); k, v single fp16 (B-side)
__device__ __half g_qh[(size_t)BB*HH*TT*DD];
__device__ __half g_ql[(size_t)BB*HH*TT*DD];
__device__ __half g_kh[(size_t)BB*HH*TT*DD];
__device__ __half g_vh[(size_t)BB*HH*TT*DD];

// ---------------------------------------------------------------------------
// Helpers (base-target ISA only: cp.async / ldmatrix / mma.sync)
// ---------------------------------------------------------------------------
__device__ __forceinline__ uint32_t smem_u32(const void* p) {
    uint32_t a;
    asm("{ .reg .u64 t; cvta.to.shared.u64 t, %1; cvt.u32.u64 %0, t; }"
        : "=r"(a) : "l"(p));
    return a;
}
#define SWZ128(off) ((off) ^ (((off) >> 3) & 0x70))

#define CP_ASYNC16(dst, src) \
    asm volatile("cp.async.cg.shared.global [%0], [%1], 16;" :: "r"(dst), "l"(src))
#define CP_COMMIT() asm volatile("cp.async.commit_group;" ::: "memory")
#define CP_WAIT(n)  asm volatile("cp.async.wait_group %0;" :: "n"(n) : "memory")

#define LDSM_X4(r, a) \
    asm volatile("ldmatrix.sync.aligned.m8n8.x4.shared.b16 {%0,%1,%2,%3}, [%4];" \
                 : "=r"((r)[0]), "=r"((r)[1]), "=r"((r)[2]), "=r"((r)[3]) : "r"(a))
#define LDSM_X4_T(r, a) \
    asm volatile("ldmatrix.sync.aligned.m8n8.x4.trans.shared.b16 {%0,%1,%2,%3}, [%4];" \
                 : "=r"((r)[0]), "=r"((r)[1]), "=r"((r)[2]), "=r"((r)[3]) : "r"(a))

#define MMA16816(d, a, b0, b1) \
    asm volatile("mma.sync.aligned.m16n8k16.row.col.f32.f16.f16.f32 " \
                 "{%0,%1,%2,%3}, {%4,%5,%6,%7}, {%8,%9}, {%0,%1,%2,%3};" \
                 : "+f"((d)[0]), "+f"((d)[1]), "+f"((d)[2]), "+f"((d)[3]) \
                 : "r"((a)[0]), "r"((a)[1]), "r"((a)[2]), "r"((a)[3]), \
                   "r"(b0), "r"(b1))

// split a float pair into fp16 hi pair + fp16 lo (residual) pair
__device__ __forceinline__ void split_pair(float a, float b, uint32_t& hi, uint32_t& lo) {
    __half2 h = __floats2half2_rn(a, b);
    float ra = a - __half2float(__low2half(h));
    float rb = b - __half2float(__high2half(h));
    __half2 l = __floats2half2_rn(ra, rb);
    hi = *(uint32_t*)&h;
    lo = *(uint32_t*)&l;
}
__device__ __forceinline__ uint32_t pack_half2(float a, float b) {
    __half2 h = __floats2half2_rn(a, b);
    return *(uint32_t*)&h;
}

// ---------------------------------------------------------------------------
// fp32 -> fp16 conversion (hi only). DST 0: x -> g_ah; 1: g_bh; 2: g_pwh.
// ---------------------------------------------------------------------------
template<int DST>
__global__ void conv_split(const float* __restrict__ src, int n4) {
    int i = blockIdx.x * blockDim.x + threadIdx.x;
    if (i >= n4) return;
    float4 v = ((const float4*)src)[i];
    __half* H = (DST == 0) ? g_ah : ((DST == 1) ? g_bh : g_pwh);
    ((uint32_t*)H)[2*i]   = pack_half2(v.x, v.y);
    ((uint32_t*)H)[2*i+1] = pack_half2(v.z, v.w);
}

// ---------------------------------------------------------------------------
// LoRA intermediate from fp32 x: t[m,r] = sum_k x[m,k]*A[r,k]
// ---------------------------------------------------------------------------
__global__ void lora_kernel_f(const float* __restrict__ X, const float* __restrict__ A) {
    int warp = (blockIdx.x * blockDim.x + threadIdx.x) >> 5;
    int lane = threadIdx.x & 31;
    const float* xr = X + (size_t)warp * CC;
    float acc[RR];
#pragma unroll
    for (int r = 0; r < RR; r++) acc[r] = 0.f;
    for (int k = lane; k < CC; k += 32) {
        float xv = xr[k];
#pragma unroll
        for (int r = 0; r < RR; r++) acc[r] = fmaf(xv, __ldg(&A[r*CC + k]), acc[r]);
    }
#pragma unroll
    for (int r = 0; r < RR; r++) {
        acc[r] += __shfl_xor_sync(0xffffffffu, acc[r], 16);
        acc[r] += __shfl_xor_sync(0xffffffffu, acc[r], 8);
        acc[r] += __shfl_xor_sync(0xffffffffu, acc[r], 4);
        acc[r] += __shfl_xor_sync(0xffffffffu, acc[r], 2);
        acc[r] += __shfl_xor_sync(0xffffffffu, acc[r], 1);
    }
    if (lane == 0) {
#pragma unroll
        for (int r = 0; r < RR; r++) g_t[(size_t)warp*RR + r] = acc[r];
    }
}

// LoRA intermediate from fp16 attention output g_ah (y).
__global__ void lora_kernel_h(const float* __restrict__ A) {
    int warp = (blockIdx.x * blockDim.x + threadIdx.x) >> 5;
    int lane = threadIdx.x & 31;
    const __half* xr = g_ah + (size_t)warp * CC;
    float acc[RR];
#pragma unroll
    for (int r = 0; r < RR; r++) acc[r] = 0.f;
    for (int k2 = lane; k2 < CC/2; k2 += 32) {
        __half2 xv2 = ((const __half2*)xr)[k2];
        float x0 = __half2float(__low2half(xv2));
        float x1 = __half2float(__high2half(xv2));
#pragma unroll
        for (int r = 0; r < RR; r++) {
            acc[r] = fmaf(x0, __ldg(&A[r*CC + 2*k2]),     acc[r]);
            acc[r] = fmaf(x1, __ldg(&A[r*CC + 2*k2 + 1]), acc[r]);
        }
    }
#pragma unroll
    for (int r = 0; r < RR; r++) {
        acc[r] += __shfl_xor_sync(0xffffffffu, acc[r], 16);
        acc[r] += __shfl_xor_sync(0xffffffffu, acc[r], 8);
        acc[r] += __shfl_xor_sync(0xffffffffu, acc[r], 4);
        acc[r] += __shfl_xor_sync(0xffffffffu, acc[r], 2);
        acc[r] += __shfl_xor_sync(0xffffffffu, acc[r], 1);
    }
    if (lane == 0) {
#pragma unroll
        for (int r = 0; r < RR; r++) g_t[(size_t)warp*RR + r] = acc[r];
    }
}

// ---------------------------------------------------------------------------
// fp16 1-term HMMA GEMM (D = Ah*Bh) + bias + rank-8 LoRA epilogue.
// CTA tile 128(M) x 256(N), 256 threads: 8 warps of 64x64, stage 48KB,
// double-buffered cp.async -> 97KB smem -> 2 CTAs/SM.
// MODE 0 (QKV): q hi/lo + k/v fp16 scatter + query/key fp32 outputs.
// MODE 1 (proj): plain [M,C] fp32 output.
// ---------------------------------------------------------------------------
#define ST_BYTES 49152u
#define OFF_AH 0u
#define OFF_B  16384u

template<int MODE>
__global__ void __launch_bounds__(256) mma_gemm(const float* __restrict__ bias,
                                                const float* __restrict__ Blora,
                                                float* __restrict__ out0,
                                                float* __restrict__ out1)
{
    extern __shared__ char smem_raw[];
    uint32_t raw = smem_u32(smem_raw);
    uint32_t sb = (raw + 1023u) & ~1023u;

    const __half* Wh = (MODE == 0) ? g_bh : g_pwh;

    int tid  = threadIdx.x;
    int wid  = tid >> 5, lane = tid & 31;
    int wm   = wid >> 2;
    int wn   = wid & 3;
    int bm = blockIdx.y * 128;
    int bn = blockIdx.x * 256;

    int lrow = tid >> 3;
    int lq   = tid & 7;

    float acc[4][8][4];
#pragma unroll
    for (int i = 0; i < 4; i++)
#pragma unroll
        for (int j = 0; j < 8; j++)
#pragma unroll
            for (int c = 0; c < 4; c++) acc[i][j][c] = 0.f;

    auto load_chunk = [&](int stage, int k0) {
        uint32_t base = sb + stage * ST_BYTES;
#pragma unroll
        for (int i = 0; i < 4; i++) {
            int row = lrow + i * 32;
            uint32_t boff = SWZ128((uint32_t)(row * 128 + lq * 16));
            size_t go = (size_t)(bm + row) * CC + k0 + lq * 8;
            CP_ASYNC16(base + OFF_AH + boff, g_ah + go);
        }
#pragma unroll
        for (int i = 0; i < 8; i++) {
            int row = lrow + i * 32;
            uint32_t boff = SWZ128((uint32_t)(row * 128 + lq * 16));
            size_t go = (size_t)(bn + row) * CC + k0 + lq * 8;
            CP_ASYNC16(base + OFF_B + boff, Wh + go);
        }
        CP_COMMIT();
    };

    const int NCHUNK = CC / 64;
    load_chunk(0, 0);

    for (int ch = 0; ch < NCHUNK; ++ch) {
        if (ch + 1 < NCHUNK) {
            load_chunk((ch + 1) & 1, (ch + 1) * 64);
            CP_WAIT(1);
        } else {
            CP_WAIT(0);
        }
        __syncthreads();
        uint32_t base = sb + (ch & 1) * ST_BYTES;

#pragma unroll
        for (int ks = 0; ks < 4; ks++) {
            uint32_t ah[4][4];
#pragma unroll
            for (int ma = 0; ma < 4; ma++) {
                int row = wm * 64 + ma * 16 + (lane & 15);
                uint32_t kb = ks * 32 + ((lane >> 4) << 4);
                uint32_t off = SWZ128((uint32_t)(row * 128) + kb);
                LDSM_X4(ah[ma], base + OFF_AH + off);
            }
#pragma unroll
            for (int nb = 0; nb < 4; nb++) {
                uint32_t b4[4];
                int row = wn * 64 + nb * 16 + (lane & 7) + ((lane >> 4) << 3);
                uint32_t kb = ks * 32 + (((lane >> 3) & 1) << 4);
                uint32_t off = SWZ128((uint32_t)(row * 128) + kb);
                LDSM_X4(b4, base + OFF_B + off);
#pragma unroll
                for (int ma = 0; ma < 4; ma++)
#pragma unroll
                    for (int h = 0; h < 2; h++)
                        MMA16816(acc[ma][nb*2+h], ah[ma], b4[2*h], b4[2*h+1]);
            }
        }
        __syncthreads();
    }

    // ---- epilogue: + bias + LoRA, write out ----
#pragma unroll
    for (int ma = 0; ma < 4; ma++) {
        int m0 = bm + wm * 64 + ma * 16 + (lane >> 2);
        int m1 = m0 + 8;
        float4 t0a = *(const float4*)&g_t[(size_t)m0 * RR];
        float4 t0b = *(const float4*)&g_t[(size_t)m0 * RR + 4];
        float4 t1a = *(const float4*)&g_t[(size_t)m1 * RR];
        float4 t1b = *(const float4*)&g_t[(size_t)m1 * RR + 4];
#pragma unroll
        for (int na = 0; na < 8; na++) {
            int n0 = bn + wn * 64 + na * 8 + (lane & 3) * 2;
            int n1 = n0 + 1;
            float4 b0a = *(const float4*)&Blora[(size_t)n0 * RR];
            float4 b0b = *(const float4*)&Blora[(size_t)n0 * RR + 4];
            float4 b1a = *(const float4*)&Blora[(size_t)n1 * RR];
            float4 b1b = *(const float4*)&Blora[(size_t)n1 * RR + 4];
            float bs0 = __ldg(&bias[n0]), bs1 = __ldg(&bias[n1]);
            float v00 = acc[ma][na][0] + bs0
                + t0a.x*b0a.x + t0a.y*b0a.y + t0a.z*b0a.z + t0a.w*b0a.w
                + t0b.x*b0b.x + t0b.y*b0b.y + t0b.z*b0b.z + t0b.w*b0b.w;
            float v01 = acc[ma][na][1] + bs1
                + t0a.x*b1a.x + t0a.y*b1a.y + t0a.z*b1a.z + t0a.w*b1a.w
                + t0b.x*b1b.x + t0b.y*b1b.y + t0b.z*b1b.z + t0b.w*b1b.w;
            float v10 = acc[ma][na][2] + bs0
                + t1a.x*b0a.x + t1a.y*b0a.y + t1a.z*b0a.z + t1a.w*b0a.w
                + t1b.x*b0b.x + t1b.y*b0b.y + t1b.z*b0b.z + t1b.w*b0b.w;
            float v11 = acc[ma][na][3] + bs1
                + t1a.x*b1a.x + t1a.y*b1a.y + t1a.z*b1a.z + t1a.w*b1a.w
                + t1b.x*b1b.x + t1b.y*b1b.y + t1b.z*b1b.z + t1b.w*b1b.w;

            if (MODE == 0) {
                int sec = n0 >> 10;            // 0=q, 1=k, 2=v
                int cci = n0 & 1023;
                int h = cci >> 6, dd = cci & 63;
                {
                    int bi = m0 >> 11, ti = m0 & 2047;
                    size_t idx = ((size_t)((bi*HH) + h)*TT + ti)*DD + dd;
                    if (sec == 0) {
                        uint32_t hp, lp; split_pair(v00, v01, hp, lp);
                        *(uint32_t*)&g_qh[idx] = hp;
                        *(uint32_t*)&g_ql[idx] = lp;
                        float2 p; p.x = v00; p.y = v01;
                        *(float2*)&out0[(size_t)m0*CC + cci] = p;
                    } else if (sec == 1) {
                        *(uint32_t*)&g_kh[idx] = pack_half2(v00, v01);
                        float2 p; p.x = v00; p.y = v01;
                        *(float2*)&out1[(size_t)m0*CC + cci] = p;
                    } else {
                        *(uint32_t*)&g_vh[idx] = pack_half2(v00, v01);
                    }
                }
                {
                    int bi = m1 >> 11, ti = m1 & 2047;
                    size_t idx = ((size_t)((bi*HH) + h)*TT + ti)*DD + dd;
                    if (sec == 0) {
                        uint32_t hp, lp; split_pair(v10, v11, hp, lp);
                        *(uint32_t*)&g_qh[idx] = hp;
                        *(uint32_t*)&g_ql[idx] = lp;
                        float2 p; p.x = v10; p.y = v11;
                        *(float2*)&out0[(size_t)m1*CC + cci] = p;
                    } else if (sec == 1) {
                        *(uint32_t*)&g_kh[idx] = pack_half2(v10, v11);
                        float2 p; p.x = v10; p.y = v11;
                        *(float2*)&out1[(size_t)m1*CC + cci] = p;
                    } else {
                        *(uint32_t*)&g_vh[idx] = pack_half2(v10, v11);
                    }
                }
            } else {
                float2 p0; p0.x = v00; p0.y = v01;
                float2 p1; p1.x = v10; p1.y = v11;
                *(float2*)&out0[(size_t)m0*CC + n0] = p0;
                *(float2*)&out0[(size_t)m1*CC + n0] = p1;
            }
        }
    }
}

// ---------------------------------------------------------------------------
// Tensor-core causal flash attention (fp16, fp32 softmax).
// CTA: 128 Q-rows, 128 threads (4 warps x 32 rows).
// S = (Qh+Ql)*K (2-term; score errors amplify), O = Ph*V (1-term).
// Q in smem (hi/lo planes), K/V single fp16 tiles 64x64 double-buffered.
// Epilogue writes fp16 y directly to g_ah (proj GEMM A operand).
// ---------------------------------------------------------------------------
#define FQ_H 0
#define FQ_L 16384
#define FKV_BASE 32768
#define FKV_STAGE 16384
#define FKV_KH 0
#define FKV_VH 8192

__global__ void __launch_bounds__(128) flash_mma(float* __restrict__ dummy) {
    extern __shared__ char smem_raw[];
    uint32_t raw = smem_u32(smem_raw);
    uint32_t sb = (raw + 1023u) & ~1023u;

    int bh = blockIdx.y;
    int qi = gridDim.x - 1 - (int)blockIdx.x;   // long blocks first
    int tid = threadIdx.x;
    int wid = tid >> 5, lane = tid & 31;
    int row0 = qi * 128;

    const __half* Qh = g_qh + ((size_t)bh*TT + row0) * DD;
    const __half* Ql = g_ql + ((size_t)bh*TT + row0) * DD;
    const __half* Kh = g_kh + (size_t)bh*TT*DD;
    const __half* Vh = g_vh + (size_t)bh*TT*DD;

    auto load_tile64 = [&](uint32_t dst, const __half* src) {
#pragma unroll
        for (int i = 0; i < 4; i++) {
            int e = tid + i * 128;
            int row = e >> 3, q = e & 7;
            CP_ASYNC16(dst + SWZ128((uint32_t)(row * 128 + q * 16)), src + row * 64 + q * 8);
        }
    };
    auto load_tile128 = [&](uint32_t dst, const __half* src) {
#pragma unroll
        for (int i = 0; i < 8; i++) {
            int e = tid + i * 128;
            int row = e >> 3, q = e & 7;
            CP_ASYNC16(dst + SWZ128((uint32_t)(row * 128 + q * 16)), src + row * 64 + q * 8);
        }
    };
    auto load_kv = [&](int stage, int j) {
        uint32_t base = sb + FKV_BASE + stage * FKV_STAGE;
        size_t o = (size_t)j * 64 * DD;
        load_tile64(base + FKV_KH, Kh + o);
        load_tile64(base + FKV_VH, Vh + o);
        CP_COMMIT();
    };

    load_tile128(sb + FQ_H, Qh);
    load_tile128(sb + FQ_L, Ql);
    CP_COMMIT();
    load_kv(0, 0);

    float oacc[2][8][4];
#pragma unroll
    for (int ma = 0; ma < 2; ma++)
#pragma unroll
        for (int i = 0; i < 8; i++)
#pragma unroll
            for (int c = 0; c < 4; c++) oacc[ma][i][c] = 0.f;
    float m_pr[2][2] = { { -1e30f, -1e30f }, { -1e30f, -1e30f } };
    float l_pr[2][2] = { { 0.f, 0.f }, { 0.f, 0.f } };

    int jmax = 2 * qi + 1;
    for (int j = 0; j <= jmax; ++j) {
        if (j < jmax) { load_kv((j + 1) & 1, j + 1); CP_WAIT(1); }
        else          { CP_WAIT(0); }
        __syncthreads();
        uint32_t kvb = sb + FKV_BASE + (j & 1) * FKV_STAGE;

        // ---- S = Q K^T (2-term: Qh*K + Ql*K) ----
        float sacc[2][8][4];
#pragma unroll
        for (int ma = 0; ma < 2; ma++)
#pragma unroll
            for (int i = 0; i < 8; i++)
#pragma unroll
                for (int c = 0; c < 4; c++) sacc[ma][i][c] = 0.f;
#pragma unroll
        for (int k = 0; k < 4; k++) {
            uint32_t qhf[2][4], qlf[2][4];
#pragma unroll
            for (int ma = 0; ma < 2; ma++) {
                int row = wid * 32 + ma * 16 + (lane & 15);
                uint32_t kb = k * 32 + ((lane >> 4) << 4);
                uint32_t off = SWZ128((uint32_t)(row * 128) + kb);
                LDSM_X4(qhf[ma], sb + FQ_H + off);
                LDSM_X4(qlf[ma], sb + FQ_L + off);
            }
#pragma unroll
            for (int np = 0; np < 4; np++) {
                uint32_t kh4[4];
                int row = np * 16 + (lane & 7) + ((lane >> 3) & 1) * 8;
                uint32_t col = k * 32 + ((lane >> 4) << 4);
                uint32_t off = SWZ128((uint32_t)(row * 128) + col);
                LDSM_X4(kh4, kvb + FKV_KH + off);
#pragma unroll
                for (int ma = 0; ma < 2; ma++) {
                    MMA16816(sacc[ma][2*np],   qhf[ma], kh4[0], kh4[2]);
                    MMA16816(sacc[ma][2*np+1], qhf[ma], kh4[1], kh4[3]);
                }
#pragma unroll
                for (int ma = 0; ma < 2; ma++) {
                    MMA16816(sacc[ma][2*np],   qlf[ma], kh4[0], kh4[2]);
                    MMA16816(sacc[ma][2*np+1], qlf[ma], kh4[1], kh4[3]);
                }
            }
        }

        // ---- scale + causal mask + online softmax (per ma) ----
        bool diag = (j >= 2 * qi);
#pragma unroll
        for (int ma = 0; ma < 2; ma++) {
            int rg0 = row0 + wid * 32 + ma * 16 + (lane >> 2);
            float mx[2] = { -1e30f, -1e30f };
#pragma unroll
            for (int na = 0; na < 8; na++) {
#pragma unroll
                for (int c = 0; c < 4; c++) {
                    float s = sacc[ma][na][c] * 0.125f;
                    if (diag) {
                        int colg = j * 64 + na * 8 + (lane & 3) * 2 + (c & 1);
                        int rowg = rg0 + ((c >> 1) << 3);
                        if (colg > rowg) s = -1e30f;
                    }
                    sacc[ma][na][c] = s;
                    mx[c >> 1] = fmaxf(mx[c >> 1], s);
                }
            }
#pragma unroll
            for (int h = 0; h < 2; h++) {
                mx[h] = fmaxf(mx[h], __shfl_xor_sync(0xffffffffu, mx[h], 1));
                mx[h] = fmaxf(mx[h], __shfl_xor_sync(0xffffffffu, mx[h], 2));
            }
            float m_new[2], alpha[2], lsum[2] = { 0.f, 0.f };
#pragma unroll
            for (int h = 0; h < 2; h++) {
                m_new[h] = fmaxf(m_pr[ma][h], mx[h]);
                alpha[h] = __expf(m_pr[ma][h] - m_new[h]);
                m_pr[ma][h] = m_new[h];
            }
#pragma unroll
            for (int na = 0; na < 8; na++) {
#pragma unroll
                for (int c = 0; c < 4; c++) {
                    float p = __expf(sacc[ma][na][c] - m_new[c >> 1]);
                    sacc[ma][na][c] = p;
                    lsum[c >> 1] += p;
                }
            }
#pragma unroll
            for (int h = 0; h < 2; h++) {
                lsum[h] += __shfl_xor_sync(0xffffffffu, lsum[h], 1);
                lsum[h] += __shfl_xor_sync(0xffffffffu, lsum[h], 2);
                l_pr[ma][h] = l_pr[ma][h] * alpha[h] + lsum[h];
            }
#pragma unroll
            for (int na = 0; na < 8; na++) {
                oacc[ma][na][0] *= alpha[0]; oacc[ma][na][1] *= alpha[0];
                oacc[ma][na][2] *= alpha[1]; oacc[ma][na][3] *= alpha[1];
            }
        }

        // ---- O += P V (1-term: Ph*V) ----
#pragma unroll
        for (int s = 0; s < 4; s++) {
            uint32_t ph[2][4];
#pragma unroll
            for (int ma = 0; ma < 2; ma++) {
                ph[ma][0] = pack_half2(sacc[ma][2*s][0],   sacc[ma][2*s][1]);
                ph[ma][1] = pack_half2(sacc[ma][2*s][2],   sacc[ma][2*s][3]);
                ph[ma][2] = pack_half2(sacc[ma][2*s+1][0], sacc[ma][2*s+1][1]);
                ph[ma][3] = pack_half2(sacc[ma][2*s+1][2], sacc[ma][2*s+1][3]);
            }
#pragma unroll
            for (int np = 0; np < 4; np++) {
                uint32_t vh4[4];
                int row = s * 16 + (lane & 7) + ((lane >> 3) & 1) * 8;
                uint32_t col = np * 32 + ((lane >> 4) << 4);
                uint32_t off = SWZ128((uint32_t)(row * 128) + col);
                LDSM_X4_T(vh4, kvb + FKV_VH + off);
#pragma unroll
                for (int ma = 0; ma < 2; ma++) {
                    MMA16816(oacc[ma][2*np],   ph[ma], vh4[0], vh4[1]);
                    MMA16816(oacc[ma][2*np+1], ph[ma], vh4[2], vh4[3]);
                }
            }
        }
        __syncthreads();
    }

    // ---- epilogue: normalize, write fp16 y -> g_ah ----
    int h = bh & (HH - 1), bi = bh >> 4;
#pragma unroll
    for (int ma = 0; ma < 2; ma++) {
        float inv0 = 1.0f / l_pr[ma][0];
        float inv1 = 1.0f / l_pr[ma][1];
        int t0 = row0 + wid * 32 + ma * 16 + (lane >> 2);
        int t1 = t0 + 8;
        int dbase = h * DD + (lane & 3) * 2;
#pragma unroll
        for (int na = 0; na < 8; na++) {
            int d = dbase + na * 8;
            size_t i0 = ((size_t)(bi*TT + t0))*CC + d;
            size_t i1 = ((size_t)(bi*TT + t1))*CC + d;
            *(uint32_t*)&g_ah[i0] = pack_half2(oacc[ma][na][0]*inv0, oacc[ma][na][1]*inv0);
            *(uint32_t*)&g_ah[i1] = pack_half2(oacc[ma][na][2]*inv1, oacc[ma][na][3]*inv1);
        }
    }
    (void)dummy;
}

// ---------------------------------------------------------------------------
extern "C" void kernel_launch(void* const* d_in, const int* in_sizes, int n_in,
                              void* d_out, int out_size) {
    const float* x  = (const float*)d_in[0];
    const float* aw = (const float*)d_in[1];
    const float* ab = (const float*)d_in[2];
    const float* aA = (const float*)d_in[3];
    const float* aB = (const float*)d_in[4];
    const float* pw = (const float*)d_in[5];
    const float* pb = (const float*)d_in[6];
    const float* pA = (const float*)d_in[7];
    const float* pB = (const float*)d_in[8];
    (void)in_sizes; (void)n_in; (void)out_size;

    float* out  = (float*)d_out;
    float* outQ = out + (size_t)MM*CC;
    float* outK = out + (size_t)2*MM*CC;

    const int SMEM_GEMM = 2 * ST_BYTES + 1024;            // 99328 B (2 CTAs/SM)
    const int SMEM_FL   = FKV_BASE + 2 * FKV_STAGE + 1024;// 66560 B (3 CTAs/SM)
    cudaFuncSetAttribute(mma_gemm<0>, cudaFuncAttributeMaxDynamicSharedMemorySize, SMEM_GEMM);
    cudaFuncSetAttribute(mma_gemm<1>, cudaFuncAttributeMaxDynamicSharedMemorySize, SMEM_GEMM);
    cudaFuncSetAttribute(flash_mma, cudaFuncAttributeMaxDynamicSharedMemorySize, SMEM_FL);

    // 1) fp16 conversions: x, c_attn_w, c_proj_w
    conv_split<0><<<(MM*CC/4 + 255)/256, 256>>>(x, MM*CC/4);
    conv_split<1><<<(NQKV*CC/4 + 255)/256, 256>>>(aw, NQKV*CC/4);
    conv_split<2><<<(CC*CC/4 + 255)/256, 256>>>(pw, CC*CC/4);
    // 2) LoRA intermediate for c_attn (from fp32 x)
    lora_kernel_f<<<MM/8, 256>>>(x, aA);
    // 3) QKV GEMM (fp16 1-term): q hi/lo + k/v scatter + query/key outputs
    mma_gemm<0><<<dim3(NQKV/256, MM/128), 256, SMEM_GEMM>>>(ab, aB, outQ, outK);
    // 4) Causal flash attention (S 2-term, PV 1-term) -> fp16 y in g_ah
    flash_mma<<<dim3(TT/128, BB*HH), 128, SMEM_FL>>>(nullptr);
    // 5) LoRA intermediate for c_proj (from fp16 y)
    lora_kernel_h<<<MM/8, 256>>>(pA);
    // 6) proj GEMM (fp16 1-term) + bias + LoRA -> out
    mma_gemm<1><<<dim3(CC/256, MM/128), 256, SMEM_GEMM>>>(pb, pB, out, nullptr);
}